// round 12
// baseline (speedup 1.0000x reference)
#include <cuda_runtime.h>
#include <cuda_fp16.h>
#include <cstdint>

#define N_NODES 20000
#define N_EDGES 160000
#define DIM 32
#define EFD 95
#define EH 64
#define NG 64
#define ZCOLS 2048      // EH * DIM
#define BN_EPS 1e-5f
#define EPB 64          // edges per fused block
#define EAS 98          // padded ea row stride (halves)
#define HSS 68          // padded hs row stride (floats)

#define XS_STRIDE 40    // Xh padded row stride (halves)
#define BS_STRIDE 36    // Bh padded row stride (halves)
#define CS_STRIDE 264   // Cs padded row stride (halves)

// ---------------- scratch (device globals) ----------------
__device__ __align__(16) __half g_Zh[(size_t)N_NODES * ZCOLS];  // 82 MB  [n][kb][o][r]
__device__ float  g_Zb[N_NODES * DIM];
__device__ float  g_agg[N_NODES * DIM];
__device__ float  g_x1[N_NODES * DIM];
__device__ float  g_pool[NG * DIM];

// ---------------- zero kernels ----------------
__global__ void k_zero_agg_pool() {
    int i = blockIdx.x * blockDim.x + threadIdx.x;
    if (i < NG * DIM) g_pool[i] = 0.f;
    if (i < N_NODES * DIM) g_agg[i] = 0.f;
}
__global__ void k_zero_agg() {
    int i = blockIdx.x * blockDim.x + threadIdx.x;
    if (i < N_NODES * DIM) g_agg[i] = 0.f;
}

// ---------------- mma helper ----------------
__device__ __forceinline__ void mma16816(float* c, const uint32_t* a,
                                         const uint32_t* b) {
    asm volatile(
        "mma.sync.aligned.m16n8k16.row.col.f32.f16.f16.f32 "
        "{%0,%1,%2,%3},{%4,%5,%6,%7},{%8,%9},{%0,%1,%2,%3};\n"
        : "+f"(c[0]), "+f"(c[1]), "+f"(c[2]), "+f"(c[3])
        : "r"(a[0]), "r"(a[1]), "r"(a[2]), "r"(a[3]), "r"(b[0]), "r"(b[1]));
}
__device__ __forceinline__ uint32_t lds_h2(const __half* p) {
    return *(const uint32_t*)p;
}

// ---------------- K2: tensor-core zgemm ----------------
// Per block: 32 nodes x 256 Z-cols (one kb). C = Xh[32x32] @ Bh^T
// Bh[j][i] (fp16, padded 36) where flat col j = o*8 + r maps W2 row kb*8+r, col i*32+o.
__global__ void __launch_bounds__(256) k_zgemm(const float* __restrict__ X,
                                               const float* __restrict__ W2) {
    __shared__ __half Xh[32 * XS_STRIDE];       // 2.5 KB
    __shared__ __half Bh[256 * BS_STRIDE];      // 18 KB
    __shared__ __half Cs[32 * CS_STRIDE];       // 16.5 KB
    int t = threadIdx.x;
    int kb = blockIdx.x;
    int n0 = blockIdx.y * 32;

    // X tile -> fp16 smem (row-major, padded)
    {
        const float* xsrc = X + (size_t)n0 * DIM;
        float4 v = *(const float4*)(xsrc + t * 4);
        int row = t >> 3, col = (t & 7) * 4;
        __half2 h0 = __floats2half2_rn(v.x, v.y);
        __half2 h1 = __floats2half2_rn(v.z, v.w);
        *(uint32_t*)&Xh[row * XS_STRIDE + col] = *(uint32_t*)&h0;
        *(uint32_t*)&Xh[row * XS_STRIDE + col + 2] = *(uint32_t*)&h1;
    }
    // W2 tile -> permuted fp16 smem: Bh[j][i]
    {
        const float* w2src = W2 + (size_t)kb * 8192;
#pragma unroll
        for (int idx = t; idx < 8192; idx += 256) {
            int r = idx >> 10, i = (idx >> 5) & 31, o = idx & 31;
            Bh[(o * 8 + r) * BS_STRIDE + i] = __float2half(w2src[idx]);
        }
    }
    __syncthreads();

    int lane = t & 31, w = t >> 5;
    int jbase = w * 32;                 // 4 n-tiles of 8 cols per warp
    int lr = lane >> 2;                 // 0..7
    int lc = lane & 3;                  // 0..3

    float c[2][4][4] = {};              // [mt][nt][reg]
#pragma unroll
    for (int ks = 0; ks < 2; ks++) {
        uint32_t a[2][4];
#pragma unroll
        for (int mt = 0; mt < 2; mt++) {
            const __half* ab = &Xh[(mt * 16 + lr) * XS_STRIDE + ks * 16 + lc * 2];
            a[mt][0] = lds_h2(ab);
            a[mt][1] = lds_h2(ab + 8 * XS_STRIDE);
            a[mt][2] = lds_h2(ab + 8);
            a[mt][3] = lds_h2(ab + 8 * XS_STRIDE + 8);
        }
#pragma unroll
        for (int nt = 0; nt < 4; nt++) {
            const __half* bb = &Bh[(jbase + nt * 8 + lr) * BS_STRIDE + ks * 16 + lc * 2];
            uint32_t b[2];
            b[0] = lds_h2(bb);
            b[1] = lds_h2(bb + 8);
#pragma unroll
            for (int mt = 0; mt < 2; mt++)
                mma16816(c[mt][nt], a[mt], b);
        }
    }
    // epilogue: fragments -> Cs (fp16)
#pragma unroll
    for (int mt = 0; mt < 2; mt++) {
#pragma unroll
        for (int nt = 0; nt < 4; nt++) {
            int col = jbase + nt * 8 + lc * 2;
            __half2 lo = __floats2half2_rn(c[mt][nt][0], c[mt][nt][1]);
            __half2 hi = __floats2half2_rn(c[mt][nt][2], c[mt][nt][3]);
            *(uint32_t*)&Cs[(mt * 16 + lr) * CS_STRIDE + col] = *(uint32_t*)&lo;
            *(uint32_t*)&Cs[(mt * 16 + lr + 8) * CS_STRIDE + col] = *(uint32_t*)&hi;
        }
    }
    __syncthreads();
    // coalesced copy-out: 32 rows x 256 halves
    {
        int row = t >> 3, seg = t & 7;
        const __half* src = &Cs[row * CS_STRIDE + seg * 32];
        __half* dst = &g_Zh[(size_t)(n0 + row) * ZCOLS + kb * 256 + seg * 32];
#pragma unroll
        for (int q = 0; q < 4; q++)
            *(uint4*)(dst + q * 8) = *(const uint4*)(src + q * 8);
    }
}

// ---------------- K2b: Zb[n,o] = sum_i X[n,i] * b2[i*32+o] ----------------
__global__ void k_zb(const float* __restrict__ X, const float* __restrict__ b2) {
    __shared__ float Bs[DIM * DIM];
    int t = threadIdx.x;
    for (int i = t; i < DIM * DIM; i += 256) Bs[i] = b2[i];
    __syncthreads();
    int n = blockIdx.x * 8 + (t >> 5);
    int o = t & 31;
    const float* xr = X + (size_t)n * DIM;
    float v = 0.f;
#pragma unroll
    for (int i = 0; i < DIM; i++) v = fmaf(xr[i], Bs[i * DIM + o], v);
    g_Zb[n * DIM + o] = v;
}

// ---------------- K3: FUSED edge MLP + scatter (r11, unchanged) ----------
__global__ void __launch_bounds__(256) k_edge_fused(const float* __restrict__ ea,
                                                    const float* __restrict__ W1,
                                                    const float* __restrict__ b1,
                                                    const int* __restrict__ esrc,
                                                    const int* __restrict__ edst) {
    __shared__ float  W1s[EFD * EH];
    __shared__ __half eash[EPB * EAS];
    __shared__ float  hs[EPB][HSS];
    int t = threadIdx.x;
    int e0 = blockIdx.x * EPB;

    for (int i = t; i < EFD * EH; i += 256) W1s[i] = W1[i];
    for (int i = t; i < EPB * EFD; i += 256) {
        int el = i / EFD, k = i - el * EFD;
        eash[el * EAS + k] = __float2half(ea[(size_t)e0 * EFD + i]);
    }
    __syncthreads();

    int lane = t & 31;
    int jg = t >> 5;
    float bj[8];
#pragma unroll
    for (int j = 0; j < 8; j++) bj[j] = b1[jg * 8 + j];

#pragma unroll
    for (int pass = 0; pass < 2; pass++) {
        int el = pass * 32 + lane;
        float acc[8];
#pragma unroll
        for (int j = 0; j < 8; j++) acc[j] = bj[j];

        const __half* ear = &eash[el * EAS];
        const float* wr = &W1s[jg * 8];
#pragma unroll 2
        for (int k = 0; k < EFD - 1; k += 2) {
            __half2 ah = *(const __half2*)(ear + k);
            float2 af = __half22float2(ah);
            float4 w00 = *(const float4*)(wr + k * EH);
            float4 w01 = *(const float4*)(wr + k * EH + 4);
            float4 w10 = *(const float4*)(wr + (k + 1) * EH);
            float4 w11 = *(const float4*)(wr + (k + 1) * EH + 4);
            acc[0] = fmaf(af.x, w00.x, acc[0]);
            acc[1] = fmaf(af.x, w00.y, acc[1]);
            acc[2] = fmaf(af.x, w00.z, acc[2]);
            acc[3] = fmaf(af.x, w00.w, acc[3]);
            acc[4] = fmaf(af.x, w01.x, acc[4]);
            acc[5] = fmaf(af.x, w01.y, acc[5]);
            acc[6] = fmaf(af.x, w01.z, acc[6]);
            acc[7] = fmaf(af.x, w01.w, acc[7]);
            acc[0] = fmaf(af.y, w10.x, acc[0]);
            acc[1] = fmaf(af.y, w10.y, acc[1]);
            acc[2] = fmaf(af.y, w10.z, acc[2]);
            acc[3] = fmaf(af.y, w10.w, acc[3]);
            acc[4] = fmaf(af.y, w11.x, acc[4]);
            acc[5] = fmaf(af.y, w11.y, acc[5]);
            acc[6] = fmaf(af.y, w11.z, acc[6]);
            acc[7] = fmaf(af.y, w11.w, acc[7]);
        }
        {
            int k = EFD - 1;
            float a = __half2float(ear[k]);
            float4 w00 = *(const float4*)(wr + k * EH);
            float4 w01 = *(const float4*)(wr + k * EH + 4);
            acc[0] = fmaf(a, w00.x, acc[0]);
            acc[1] = fmaf(a, w00.y, acc[1]);
            acc[2] = fmaf(a, w00.z, acc[2]);
            acc[3] = fmaf(a, w00.w, acc[3]);
            acc[4] = fmaf(a, w01.x, acc[4]);
            acc[5] = fmaf(a, w01.y, acc[5]);
            acc[6] = fmaf(a, w01.z, acc[6]);
            acc[7] = fmaf(a, w01.w, acc[7]);
        }
        float4 r0 = make_float4(fmaxf(acc[0], 0.f), fmaxf(acc[1], 0.f),
                                fmaxf(acc[2], 0.f), fmaxf(acc[3], 0.f));
        float4 r1 = make_float4(fmaxf(acc[4], 0.f), fmaxf(acc[5], 0.f),
                                fmaxf(acc[6], 0.f), fmaxf(acc[7], 0.f));
        *(float4*)&hs[el][jg * 8] = r0;
        *(float4*)&hs[el][jg * 8 + 4] = r1;
    }
    __syncthreads();

    int wid = t >> 5;
#pragma unroll
    for (int rnd = 0; rnd < 8; rnd++) {
        int eloc = rnd * 8 + wid;
        int e = e0 + eloc;
        int s = esrc[e], d = edst[e];
        const __half* zr = g_Zh + (size_t)s * ZCOLS + lane * 8;
        const float* hr = hs[eloc];
        float msg0 = g_Zb[s * DIM + lane];
        float msg1 = 0.f;
#pragma unroll
        for (int kb = 0; kb < 8; kb += 2) {
            uint4 v0 = __ldg((const uint4*)(zr + kb * 256));
            uint4 v1 = __ldg((const uint4*)(zr + (kb + 1) * 256));
            float4 h0 = *(const float4*)&hr[kb * 8];
            float4 h1 = *(const float4*)&hr[kb * 8 + 4];
            float4 h2 = *(const float4*)&hr[kb * 8 + 8];
            float4 h3 = *(const float4*)&hr[kb * 8 + 12];
            float2 a0 = __half22float2(*(__half2*)&v0.x);
            float2 a1 = __half22float2(*(__half2*)&v0.y);
            float2 a2 = __half22float2(*(__half2*)&v0.z);
            float2 a3 = __half22float2(*(__half2*)&v0.w);
            float2 b0 = __half22float2(*(__half2*)&v1.x);
            float2 b1 = __half22float2(*(__half2*)&v1.y);
            float2 b2 = __half22float2(*(__half2*)&v1.z);
            float2 b3 = __half22float2(*(__half2*)&v1.w);
            msg0 = fmaf(h0.x, a0.x, msg0);
            msg1 = fmaf(h0.y, a0.y, msg1);
            msg0 = fmaf(h0.z, a1.x, msg0);
            msg1 = fmaf(h0.w, a1.y, msg1);
            msg0 = fmaf(h1.x, a2.x, msg0);
            msg1 = fmaf(h1.y, a2.y, msg1);
            msg0 = fmaf(h1.z, a3.x, msg0);
            msg1 = fmaf(h1.w, a3.y, msg1);
            msg0 = fmaf(h2.x, b0.x, msg0);
            msg1 = fmaf(h2.y, b0.y, msg1);
            msg0 = fmaf(h2.z, b1.x, msg0);
            msg1 = fmaf(h2.w, b1.y, msg1);
            msg0 = fmaf(h3.x, b2.x, msg0);
            msg1 = fmaf(h3.y, b2.y, msg1);
            msg0 = fmaf(h3.z, b3.x, msg0);
            msg1 = fmaf(h3.w, b3.y, msg1);
        }
        atomicAdd(&g_agg[d * DIM + lane], msg0 + msg1);
    }
}

// ---------------- K4: node update ----------------
template <bool POOL>
__global__ void k_node_update(const float* __restrict__ xin,
                              const float* __restrict__ root,
                              const float* __restrict__ bias,
                              const float* __restrict__ bng,
                              const float* __restrict__ bnb,
                              const float* __restrict__ bnrm,
                              const float* __restrict__ bnrv,
                              float* __restrict__ xout,
                              const int* __restrict__ batch) {
    __shared__ float Rs[DIM * DIM];
    int t = threadIdx.x;
    for (int i = t; i < DIM * DIM; i += 256) Rs[i] = root[i];
    __syncthreads();
    int n = blockIdx.x * 8 + (t >> 5);
    int o = t & 31;
    const float* xr = xin + (size_t)n * DIM;
    float v = g_agg[n * DIM + o] + bias[o];
#pragma unroll
    for (int i = 0; i < DIM; i++) v = fmaf(xr[i], Rs[i * DIM + o], v);
    v = (v - bnrm[o]) * rsqrtf(bnrv[o] + BN_EPS) * bng[o] + bnb[o];
    v = fmaxf(v, 0.f);
    if (POOL) {
        int b = batch[n];
        atomicMax((int*)&g_pool[b * DIM + o], __float_as_int(v));
    } else {
        xout[n * DIM + o] = v;
    }
}

// ---------------- K6: head ----------------
__global__ void k_head(const float* __restrict__ l1W, const float* __restrict__ l1b,
                       const float* __restrict__ l2W, const float* __restrict__ l2b,
                       float* __restrict__ out) {
    int g = threadIdx.x;
    const float* pr = &g_pool[g * DIM];
    float tbuf[DIM];
#pragma unroll
    for (int j = 0; j < DIM; j++) {
        float v = l1b[j];
#pragma unroll
        for (int i = 0; i < DIM; i++) v = fmaf(pr[i], l1W[i * DIM + j], v);
        tbuf[j] = fmaxf(v, 0.f);
    }
#pragma unroll
    for (int c = 0; c < 2; c++) {
        float v = l2b[c];
#pragma unroll
        for (int j = 0; j < DIM; j++) v = fmaf(tbuf[j], l2W[j * 2 + c], v);
        out[g * 2 + c] = v;
    }
}

// ---------------- launch ----------------
extern "C" void kernel_launch(void* const* d_in, const int* in_sizes, int n_in,
                              void* d_out, int out_size) {
    const float* x     = (const float*)d_in[0];
    const int*   esrc  = (const int*)d_in[1];
    const int*   edst  = (const int*)d_in[2];
    const float* ea    = (const float*)d_in[3];
    const int*   batch = (const int*)d_in[4];

    const float* c0W1 = (const float*)d_in[5];
    const float* c0b1 = (const float*)d_in[6];
    const float* c0W2 = (const float*)d_in[7];
    const float* c0b2 = (const float*)d_in[8];
    const float* c0rt = (const float*)d_in[9];
    const float* c0bs = (const float*)d_in[10];
    const float* bn0g = (const float*)d_in[11];
    const float* bn0b = (const float*)d_in[12];
    const float* bn0m = (const float*)d_in[13];
    const float* bn0v = (const float*)d_in[14];

    const float* c1W1 = (const float*)d_in[15];
    const float* c1b1 = (const float*)d_in[16];
    const float* c1W2 = (const float*)d_in[17];
    const float* c1b2 = (const float*)d_in[18];
    const float* c1rt = (const float*)d_in[19];
    const float* c1bs = (const float*)d_in[20];
    const float* bn1g = (const float*)d_in[21];
    const float* bn1b = (const float*)d_in[22];
    const float* bn1m = (const float*)d_in[23];
    const float* bn1v = (const float*)d_in[24];

    const float* l1W = (const float*)d_in[25];
    const float* l1b = (const float*)d_in[26];
    const float* l2W = (const float*)d_in[27];
    const float* l2b = (const float*)d_in[28];

    float* out = (float*)d_out;

    void* px1 = nullptr;
    cudaGetSymbolAddress(&px1, g_x1);
    float* x1 = (float*)px1;

    dim3 zg(8, N_NODES / 32);

    // ---- conv0 ----
    k_zero_agg_pool<<<(N_NODES * DIM + 255) / 256, 256>>>();
    k_zgemm<<<zg, 256>>>(x, c0W2);
    k_zb<<<N_NODES / 8, 256>>>(x, c0b2);
    k_edge_fused<<<N_EDGES / EPB, 256>>>(ea, c0W1, c0b1, esrc, edst);
    k_node_update<false><<<N_NODES / 8, 256>>>(x, c0rt, c0bs, bn0g, bn0b,
                                               bn0m, bn0v, x1, nullptr);

    // ---- conv1 ----
    k_zero_agg<<<(N_NODES * DIM + 255) / 256, 256>>>();
    k_zgemm<<<zg, 256>>>(x1, c1W2);
    k_zb<<<N_NODES / 8, 256>>>(x1, c1b2);
    k_edge_fused<<<N_EDGES / EPB, 256>>>(ea, c1W1, c1b1, esrc, edst);
    k_node_update<true><<<N_NODES / 8, 256>>>(x1, c1rt, c1bs, bn1g, bn1b,
                                              bn1m, bn1v, nullptr, batch);

    // ---- head ----
    k_head<<<1, NG>>>(l1W, l1b, l2W, l2b, out);
}

// round 13
// speedup vs baseline: 1.4610x; 1.4610x over previous
#include <cuda_runtime.h>
#include <cuda_fp16.h>
#include <cstdint>

#define N_NODES 20000
#define N_EDGES 160000
#define DIM 32
#define EFD 95
#define EH 64
#define NG 64
#define ZCOLS 2048      // EH * DIM
#define BN_EPS 1e-5f
#define EPB 64          // edges per fused block
#define KP 104          // padded k stride (halves) for eash/W1T: 16B-aligned, conflict-free
#define HSS 68          // hs row stride (floats)

// ---------------- scratch (device globals) ----------------
__device__ __align__(16) __half g_Zh[(size_t)N_NODES * ZCOLS];  // 82 MB  [n][kb][o][r]
__device__ float  g_Zb[N_NODES * DIM];
__device__ float  g_agg[N_NODES * DIM];
__device__ float  g_x1[N_NODES * DIM];
__device__ float  g_pool[NG * DIM];

// ---------------- zero kernels ----------------
__global__ void k_zero_agg_pool() {
    int i = blockIdx.x * blockDim.x + threadIdx.x;
    if (i < NG * DIM) g_pool[i] = 0.f;
    if (i < N_NODES * DIM) g_agg[i] = 0.f;
}
__global__ void k_zero_agg() {
    int i = blockIdx.x * blockDim.x + threadIdx.x;
    if (i < N_NODES * DIM) g_agg[i] = 0.f;
}

// ---------------- mma helper (validated in round 12) ----------------
__device__ __forceinline__ void mma16816(float* c, const uint32_t* a,
                                         const uint32_t* b) {
    asm volatile(
        "mma.sync.aligned.m16n8k16.row.col.f32.f16.f16.f32 "
        "{%0,%1,%2,%3},{%4,%5,%6,%7},{%8,%9},{%0,%1,%2,%3};\n"
        : "+f"(c[0]), "+f"(c[1]), "+f"(c[2]), "+f"(c[3])
        : "r"(a[0]), "r"(a[1]), "r"(a[2]), "r"(a[3]), "r"(b[0]), "r"(b[1]));
}
__device__ __forceinline__ uint32_t lds_h2(const __half* p) {
    return *(const uint32_t*)p;
}

// ---------------- K2: Zh[n][kb][o][r] (round-3 scalar core, known 72us) ---
__global__ void __launch_bounds__(256) k_zgemm(const float* __restrict__ X,
                                               const float* __restrict__ W2) {
    __shared__ float Xs[32 * DIM];
    __shared__ float Bs[8 * 32 * 32];
    int t = threadIdx.x;
    int kb = blockIdx.x;
    int n0 = blockIdx.y * 32;

    for (int i = t; i < 32 * DIM; i += 256)
        Xs[i] = X[(size_t)n0 * DIM + i];
    const float* w2src = W2 + (size_t)kb * 8192;
#pragma unroll
    for (int i = 0; i < 8192; i += 256)
        Bs[i + t] = w2src[i + t];
    __syncthreads();

    int o = t & 31, trow = t >> 5;
    float acc[4][8] = {};
#pragma unroll
    for (int i = 0; i < DIM; i++) {
        float b[8];
#pragma unroll
        for (int r = 0; r < 8; r++) b[r] = Bs[r * 1024 + i * 32 + o];
#pragma unroll
        for (int rr = 0; rr < 4; rr++) {
            float a = Xs[(trow * 4 + rr) * DIM + i];
#pragma unroll
            for (int r = 0; r < 8; r++)
                acc[rr][r] = fmaf(a, b[r], acc[rr][r]);
        }
    }
#pragma unroll
    for (int rr = 0; rr < 4; rr++) {
        int n = n0 + trow * 4 + rr;
        __half2 p0 = __floats2half2_rn(acc[rr][0], acc[rr][1]);
        __half2 p1 = __floats2half2_rn(acc[rr][2], acc[rr][3]);
        __half2 p2 = __floats2half2_rn(acc[rr][4], acc[rr][5]);
        __half2 p3 = __floats2half2_rn(acc[rr][6], acc[rr][7]);
        uint4 pk = make_uint4(*(uint32_t*)&p0, *(uint32_t*)&p1,
                              *(uint32_t*)&p2, *(uint32_t*)&p3);
        *(uint4*)&g_Zh[(size_t)n * ZCOLS + kb * 256 + o * 8] = pk;
    }
}

// ---------------- K2b: Zb[n,o] = sum_i X[n,i] * b2[i*32+o] ----------------
__global__ void k_zb(const float* __restrict__ X, const float* __restrict__ b2) {
    __shared__ float Bs[DIM * DIM];
    int t = threadIdx.x;
    for (int i = t; i < DIM * DIM; i += 256) Bs[i] = b2[i];
    __syncthreads();
    int n = blockIdx.x * 8 + (t >> 5);
    int o = t & 31;
    const float* xr = X + (size_t)n * DIM;
    float v = 0.f;
#pragma unroll
    for (int i = 0; i < DIM; i++) v = fmaf(xr[i], Bs[i * DIM + o], v);
    g_Zb[n * DIM + o] = v;
}

// ---------------- K3: FUSED edge MLP (HMMA) + scatter ----------------
// Phase 1: hs = relu([64xEFD ea] @ [EFD x 64 W1] + b1) via m16n8k16 tensor core.
//   eash [el][KP] fp16, W1T [j][KP] fp16 (transposed, zero-padded k=95..).
//   Frag loads are direct LDS, conflict-free (bank = 20*lr + lc mod 32, a bijection).
// Phase 2: unchanged (warp per edge, Z gather from L2, atomicAdd).
__global__ void __launch_bounds__(256) k_edge_fused(const float* __restrict__ ea,
                                                    const float* __restrict__ W1,
                                                    const float* __restrict__ b1,
                                                    const int* __restrict__ esrc,
                                                    const int* __restrict__ edst) {
    __shared__ __half eash[EPB * KP];       // 13312 B
    __shared__ __half W1T[EH * KP];         // 13312 B
    __shared__ float  hs[EPB][HSS];         // 17408 B  (~44 KB total)
    int t = threadIdx.x;
    int e0 = blockIdx.x * EPB;

    // eash[el][k] = fp16(ea[e0+el][k]), zero k=95
    for (int idx = t; idx < EPB * 96; idx += 256) {
        int el = idx / 96, k = idx - el * 96;
        eash[el * KP + k] = (k < EFD)
            ? __float2half(ea[(size_t)(e0 + el) * EFD + k]) : __half(0.f);
    }
    // W1T[j][k] = fp16(W1[k][j]), zero k=95
    for (int idx = t; idx < EH * 96; idx += 256) {
        int k = idx >> 6, j = idx & 63;
        W1T[j * KP + k] = (k < EFD) ? __float2half(W1[k * EH + j]) : __half(0.f);
    }
    __syncthreads();

    int lane = t & 31, w = t >> 5;
    int lr = lane >> 2, lc = lane & 3;

    // ---- phase 1: 24 MMAs per warp ----
    {
        int mbase = (w & 3) * 16;           // edge tile (16 edges)
        int jbase = (w >> 2) * 32;          // 4 j-tiles of 8
        float c[4][4] = {};
#pragma unroll
        for (int ks = 0; ks < 6; ks++) {
            const __half* ab = &eash[(mbase + lr) * KP + ks * 16 + lc * 2];
            uint32_t a[4];
            a[0] = lds_h2(ab);
            a[1] = lds_h2(ab + 8 * KP);
            a[2] = lds_h2(ab + 8);
            a[3] = lds_h2(ab + 8 * KP + 8);
#pragma unroll
            for (int nt = 0; nt < 4; nt++) {
                const __half* bb = &W1T[(jbase + nt * 8 + lr) * KP + ks * 16 + lc * 2];
                uint32_t b[2];
                b[0] = lds_h2(bb);
                b[1] = lds_h2(bb + 8);
                mma16816(c[nt], a, b);
            }
        }
        // epilogue: +bias, relu, -> hs
#pragma unroll
        for (int nt = 0; nt < 4; nt++) {
            int j = jbase + nt * 8 + lc * 2;
            float bx = b1[j], by = b1[j + 1];
            float2 lo = make_float2(fmaxf(c[nt][0] + bx, 0.f),
                                    fmaxf(c[nt][1] + by, 0.f));
            float2 hi = make_float2(fmaxf(c[nt][2] + bx, 0.f),
                                    fmaxf(c[nt][3] + by, 0.f));
            *(float2*)&hs[mbase + lr][j] = lo;
            *(float2*)&hs[mbase + lr + 8][j] = hi;
        }
    }
    __syncthreads();

    // ---- phase 2: scatter (warp per edge, 8 rounds) ----
#pragma unroll
    for (int rnd = 0; rnd < 8; rnd++) {
        int eloc = rnd * 8 + w;
        int e = e0 + eloc;
        int s = esrc[e], d = edst[e];
        const __half* zr = g_Zh + (size_t)s * ZCOLS + lane * 8;
        const float* hr = hs[eloc];
        float msg0 = g_Zb[s * DIM + lane];
        float msg1 = 0.f;
#pragma unroll
        for (int kb = 0; kb < 8; kb += 2) {
            uint4 v0 = __ldg((const uint4*)(zr + kb * 256));
            uint4 v1 = __ldg((const uint4*)(zr + (kb + 1) * 256));
            float4 h0 = *(const float4*)&hr[kb * 8];
            float4 h1 = *(const float4*)&hr[kb * 8 + 4];
            float4 h2 = *(const float4*)&hr[kb * 8 + 8];
            float4 h3 = *(const float4*)&hr[kb * 8 + 12];
            float2 a0 = __half22float2(*(__half2*)&v0.x);
            float2 a1 = __half22float2(*(__half2*)&v0.y);
            float2 a2 = __half22float2(*(__half2*)&v0.z);
            float2 a3 = __half22float2(*(__half2*)&v0.w);
            float2 b0 = __half22float2(*(__half2*)&v1.x);
            float2 b1f = __half22float2(*(__half2*)&v1.y);
            float2 b2f = __half22float2(*(__half2*)&v1.z);
            float2 b3f = __half22float2(*(__half2*)&v1.w);
            msg0 = fmaf(h0.x, a0.x, msg0);
            msg1 = fmaf(h0.y, a0.y, msg1);
            msg0 = fmaf(h0.z, a1.x, msg0);
            msg1 = fmaf(h0.w, a1.y, msg1);
            msg0 = fmaf(h1.x, a2.x, msg0);
            msg1 = fmaf(h1.y, a2.y, msg1);
            msg0 = fmaf(h1.z, a3.x, msg0);
            msg1 = fmaf(h1.w, a3.y, msg1);
            msg0 = fmaf(h2.x, b0.x, msg0);
            msg1 = fmaf(h2.y, b0.y, msg1);
            msg0 = fmaf(h2.z, b1f.x, msg0);
            msg1 = fmaf(h2.w, b1f.y, msg1);
            msg0 = fmaf(h3.x, b2f.x, msg0);
            msg1 = fmaf(h3.y, b2f.y, msg1);
            msg0 = fmaf(h3.z, b3f.x, msg0);
            msg1 = fmaf(h3.w, b3f.y, msg1);
        }
        atomicAdd(&g_agg[d * DIM + lane], msg0 + msg1);
    }
}

// ---------------- K4: node update ----------------
template <bool POOL>
__global__ void k_node_update(const float* __restrict__ xin,
                              const float* __restrict__ root,
                              const float* __restrict__ bias,
                              const float* __restrict__ bng,
                              const float* __restrict__ bnb,
                              const float* __restrict__ bnrm,
                              const float* __restrict__ bnrv,
                              float* __restrict__ xout,
                              const int* __restrict__ batch) {
    __shared__ float Rs[DIM * DIM];
    int t = threadIdx.x;
    for (int i = t; i < DIM * DIM; i += 256) Rs[i] = root[i];
    __syncthreads();
    int n = blockIdx.x * 8 + (t >> 5);
    int o = t & 31;
    const float* xr = xin + (size_t)n * DIM;
    float v = g_agg[n * DIM + o] + bias[o];
#pragma unroll
    for (int i = 0; i < DIM; i++) v = fmaf(xr[i], Rs[i * DIM + o], v);
    v = (v - bnrm[o]) * rsqrtf(bnrv[o] + BN_EPS) * bng[o] + bnb[o];
    v = fmaxf(v, 0.f);
    if (POOL) {
        int b = batch[n];
        atomicMax((int*)&g_pool[b * DIM + o], __float_as_int(v));
    } else {
        xout[n * DIM + o] = v;
    }
}

// ---------------- K6: head ----------------
__global__ void k_head(const float* __restrict__ l1W, const float* __restrict__ l1b,
                       const float* __restrict__ l2W, const float* __restrict__ l2b,
                       float* __restrict__ out) {
    int g = threadIdx.x;
    const float* pr = &g_pool[g * DIM];
    float tbuf[DIM];
#pragma unroll
    for (int j = 0; j < DIM; j++) {
        float v = l1b[j];
#pragma unroll
        for (int i = 0; i < DIM; i++) v = fmaf(pr[i], l1W[i * DIM + j], v);
        tbuf[j] = fmaxf(v, 0.f);
    }
#pragma unroll
    for (int c = 0; c < 2; c++) {
        float v = l2b[c];
#pragma unroll
        for (int j = 0; j < DIM; j++) v = fmaf(tbuf[j], l2W[j * 2 + c], v);
        out[g * 2 + c] = v;
    }
}

// ---------------- launch ----------------
extern "C" void kernel_launch(void* const* d_in, const int* in_sizes, int n_in,
                              void* d_out, int out_size) {
    const float* x     = (const float*)d_in[0];
    const int*   esrc  = (const int*)d_in[1];
    const int*   edst  = (const int*)d_in[2];
    const float* ea    = (const float*)d_in[3];
    const int*   batch = (const int*)d_in[4];

    const float* c0W1 = (const float*)d_in[5];
    const float* c0b1 = (const float*)d_in[6];
    const float* c0W2 = (const float*)d_in[7];
    const float* c0b2 = (const float*)d_in[8];
    const float* c0rt = (const float*)d_in[9];
    const float* c0bs = (const float*)d_in[10];
    const float* bn0g = (const float*)d_in[11];
    const float* bn0b = (const float*)d_in[12];
    const float* bn0m = (const float*)d_in[13];
    const float* bn0v = (const float*)d_in[14];

    const float* c1W1 = (const float*)d_in[15];
    const float* c1b1 = (const float*)d_in[16];
    const float* c1W2 = (const float*)d_in[17];
    const float* c1b2 = (const float*)d_in[18];
    const float* c1rt = (const float*)d_in[19];
    const float* c1bs = (const float*)d_in[20];
    const float* bn1g = (const float*)d_in[21];
    const float* bn1b = (const float*)d_in[22];
    const float* bn1m = (const float*)d_in[23];
    const float* bn1v = (const float*)d_in[24];

    const float* l1W = (const float*)d_in[25];
    const float* l1b = (const float*)d_in[26];
    const float* l2W = (const float*)d_in[27];
    const float* l2b = (const float*)d_in[28];

    float* out = (float*)d_out;

    void* px1 = nullptr;
    cudaGetSymbolAddress(&px1, g_x1);
    float* x1 = (float*)px1;

    dim3 zg(8, N_NODES / 32);

    // ---- conv0 ----
    k_zero_agg_pool<<<(N_NODES * DIM + 255) / 256, 256>>>();
    k_zgemm<<<zg, 256>>>(x, c0W2);
    k_zb<<<N_NODES / 8, 256>>>(x, c0b2);
    k_edge_fused<<<N_EDGES / EPB, 256>>>(ea, c0W1, c0b1, esrc, edst);
    k_node_update<false><<<N_NODES / 8, 256>>>(x, c0rt, c0bs, bn0g, bn0b,
                                               bn0m, bn0v, x1, nullptr);

    // ---- conv1 ----
    k_zero_agg<<<(N_NODES * DIM + 255) / 256, 256>>>();
    k_zgemm<<<zg, 256>>>(x1, c1W2);
    k_zb<<<N_NODES / 8, 256>>>(x1, c1b2);
    k_edge_fused<<<N_EDGES / EPB, 256>>>(ea, c1W1, c1b1, esrc, edst);
    k_node_update<true><<<N_NODES / 8, 256>>>(x1, c1rt, c1bs, bn1g, bn1b,
                                              bn1m, bn1v, nullptr, batch);

    // ---- head ----
    k_head<<<1, NG>>>(l1W, l1b, l2W, l2b, out);
}

// round 14
// speedup vs baseline: 1.6632x; 1.1384x over previous
#include <cuda_runtime.h>
#include <cuda_fp16.h>
#include <cstdint>

#define N_NODES 20000
#define N_EDGES 160000
#define DIM 32
#define EFD 95
#define EH 64
#define NG 64
#define ZCOLS 2048      // EH * DIM
#define BN_EPS 1e-5f
#define EPB 64          // edges per fused block
#define KP 104          // padded k stride (halves) for eash/W1T
#define HSS 68          // hs row stride (floats)

#define XSP 40          // Xh row stride (halves)
#define BSP 36          // Bh row stride (halves)
#define CSP 72          // Cs row stride (halves), 64-col chunk + pad

// ---------------- scratch (device globals) ----------------
__device__ __align__(16) __half g_Zh[(size_t)N_NODES * ZCOLS];  // 82 MB  [n][kb][o][r]
__device__ float  g_Zb[N_NODES * DIM];
__device__ float  g_agg[N_NODES * DIM];
__device__ float  g_x1[N_NODES * DIM];
__device__ float  g_pool[NG * DIM];

// ---------------- zero kernels ----------------
__global__ void k_zero_agg_pool() {
    int i = blockIdx.x * blockDim.x + threadIdx.x;
    if (i < NG * DIM) g_pool[i] = 0.f;
    if (i < N_NODES * DIM) g_agg[i] = 0.f;
}
__global__ void k_zero_agg() {
    int i = blockIdx.x * blockDim.x + threadIdx.x;
    if (i < N_NODES * DIM) g_agg[i] = 0.f;
}

// ---------------- mma helper (fragment mappings validated in r12/r13) -----
__device__ __forceinline__ void mma16816(float* c, const uint32_t* a,
                                         const uint32_t* b) {
    asm volatile(
        "mma.sync.aligned.m16n8k16.row.col.f32.f16.f16.f32 "
        "{%0,%1,%2,%3},{%4,%5,%6,%7},{%8,%9},{%0,%1,%2,%3};\n"
        : "+f"(c[0]), "+f"(c[1]), "+f"(c[2]), "+f"(c[3])
        : "r"(a[0]), "r"(a[1]), "r"(a[2]), "r"(a[3]), "r"(b[0]), "r"(b[1]));
}
__device__ __forceinline__ uint32_t lds_h2(const __half* p) {
    return *(const uint32_t*)p;
}

// ---------------- K2: tensor-core zgemm, 128-node tiles ----------------
// Per block: 128 nodes x 256 Z-cols (one kb). Warp w owns rows w*16..w*16+15.
// 64 MMAs/warp; epilogue staged via Cs in 4 chunks of 64 cols.
__global__ void __launch_bounds__(256) k_zgemm(const float* __restrict__ X,
                                               const float* __restrict__ W2) {
    __shared__ __half Xh[128 * XSP];        // 10240 B
    __shared__ __half Bh[256 * BSP];        // 18432 B
    __shared__ __half Cs[128 * CSP];        // 18432 B   (47104 total)
    int t = threadIdx.x;
    int kb = blockIdx.x;
    int n0 = blockIdx.y * 128;

    // X tile -> fp16 (row-major, padded, zero beyond N)
#pragma unroll
    for (int idx = t; idx < 1024; idx += 256) {
        int row = idx >> 3, q = idx & 7;
        int n = n0 + row;
        float4 v = (n < N_NODES) ? *(const float4*)(X + (size_t)n * DIM + q * 4)
                                 : make_float4(0.f, 0.f, 0.f, 0.f);
        __half2 h0 = __floats2half2_rn(v.x, v.y);
        __half2 h1 = __floats2half2_rn(v.z, v.w);
        *(uint32_t*)&Xh[row * XSP + q * 4] = *(uint32_t*)&h0;
        *(uint32_t*)&Xh[row * XSP + q * 4 + 2] = *(uint32_t*)&h1;
    }
    // W2 tile -> Bh[j][i], j = o*8+r  (r12-validated permutation)
    {
        const float* w2src = W2 + (size_t)kb * 8192;
#pragma unroll
        for (int idx = t; idx < 8192; idx += 256) {
            int r = idx >> 10, i = (idx >> 5) & 31, o = idx & 31;
            Bh[(o * 8 + r) * BSP + i] = __float2half(w2src[idx]);
        }
    }
    __syncthreads();

    int lane = t & 31, w = t >> 5;
    int lr = lane >> 2, lc = lane & 3;
    int m0 = w * 16;

    // A fragments (kept across all chunks)
    uint32_t a[2][4];
#pragma unroll
    for (int ks = 0; ks < 2; ks++) {
        const __half* ab = &Xh[(m0 + lr) * XSP + ks * 16 + lc * 2];
        a[ks][0] = lds_h2(ab);
        a[ks][1] = lds_h2(ab + 8 * XSP);
        a[ks][2] = lds_h2(ab + 8);
        a[ks][3] = lds_h2(ab + 8 * XSP + 8);
    }

#pragma unroll
    for (int ng = 0; ng < 4; ng++) {
        float c[8][4] = {};
#pragma unroll
        for (int nt = 0; nt < 8; nt++) {
            int j0 = ng * 64 + nt * 8;
#pragma unroll
            for (int ks = 0; ks < 2; ks++) {
                const __half* bb = &Bh[(j0 + lr) * BSP + ks * 16 + lc * 2];
                uint32_t b[2];
                b[0] = lds_h2(bb);
                b[1] = lds_h2(bb + 8);
                mma16816(c[nt], a[ks], b);
            }
        }
        __syncthreads();        // prior chunk's copy-out complete
        // frag -> Cs (warp-exclusive rows; bank = 4*lr + lc, conflict-free)
#pragma unroll
        for (int nt = 0; nt < 8; nt++) {
            int jj = nt * 8 + lc * 2;
            __half2 lo = __floats2half2_rn(c[nt][0], c[nt][1]);
            __half2 hi = __floats2half2_rn(c[nt][2], c[nt][3]);
            *(uint32_t*)&Cs[(m0 + lr) * CSP + jj] = *(uint32_t*)&lo;
            *(uint32_t*)&Cs[(m0 + lr + 8) * CSP + jj] = *(uint32_t*)&hi;
        }
        __syncthreads();
        // coalesced copy-out: 128 rows x 64 halves
#pragma unroll
        for (int idx = t; idx < 1024; idx += 256) {
            int row = idx >> 3, seg = idx & 7;
            int n = n0 + row;
            if (n < N_NODES)
                *(uint4*)&g_Zh[(size_t)n * ZCOLS + kb * 256 + ng * 64 + seg * 8] =
                    *(const uint4*)&Cs[row * CSP + seg * 8];
        }
    }
}

// ---------------- K2b: Zb[n,o] = sum_i X[n,i] * b2[i*32+o] ----------------
__global__ void k_zb(const float* __restrict__ X, const float* __restrict__ b2) {
    __shared__ float Bs[DIM * DIM];
    int t = threadIdx.x;
    for (int i = t; i < DIM * DIM; i += 256) Bs[i] = b2[i];
    __syncthreads();
    int n = blockIdx.x * 8 + (t >> 5);
    int o = t & 31;
    const float* xr = X + (size_t)n * DIM;
    float v = 0.f;
#pragma unroll
    for (int i = 0; i < DIM; i++) v = fmaf(xr[i], Bs[i * DIM + o], v);
    g_Zb[n * DIM + o] = v;
}

// ---------------- K3: FUSED edge MLP (HMMA) + scatter (r13, unchanged) ----
__global__ void __launch_bounds__(256) k_edge_fused(const float* __restrict__ ea,
                                                    const float* __restrict__ W1,
                                                    const float* __restrict__ b1,
                                                    const int* __restrict__ esrc,
                                                    const int* __restrict__ edst) {
    __shared__ __half eash[EPB * KP];
    __shared__ __half W1T[EH * KP];
    __shared__ float  hs[EPB][HSS];
    int t = threadIdx.x;
    int e0 = blockIdx.x * EPB;

    for (int idx = t; idx < EPB * 96; idx += 256) {
        int el = idx / 96, k = idx - el * 96;
        eash[el * KP + k] = (k < EFD)
            ? __float2half(ea[(size_t)(e0 + el) * EFD + k]) : __half(0.f);
    }
    for (int idx = t; idx < EH * 96; idx += 256) {
        int k = idx >> 6, j = idx & 63;
        W1T[j * KP + k] = (k < EFD) ? __float2half(W1[k * EH + j]) : __half(0.f);
    }
    __syncthreads();

    int lane = t & 31, w = t >> 5;
    int lr = lane >> 2, lc = lane & 3;

    {
        int mbase = (w & 3) * 16;
        int jbase = (w >> 2) * 32;
        float c[4][4] = {};
#pragma unroll
        for (int ks = 0; ks < 6; ks++) {
            const __half* ab = &eash[(mbase + lr) * KP + ks * 16 + lc * 2];
            uint32_t a[4];
            a[0] = lds_h2(ab);
            a[1] = lds_h2(ab + 8 * KP);
            a[2] = lds_h2(ab + 8);
            a[3] = lds_h2(ab + 8 * KP + 8);
#pragma unroll
            for (int nt = 0; nt < 4; nt++) {
                const __half* bb = &W1T[(jbase + nt * 8 + lr) * KP + ks * 16 + lc * 2];
                uint32_t b[2];
                b[0] = lds_h2(bb);
                b[1] = lds_h2(bb + 8);
                mma16816(c[nt], a, b);
            }
        }
#pragma unroll
        for (int nt = 0; nt < 4; nt++) {
            int j = jbase + nt * 8 + lc * 2;
            float bx = b1[j], by = b1[j + 1];
            float2 lo = make_float2(fmaxf(c[nt][0] + bx, 0.f),
                                    fmaxf(c[nt][1] + by, 0.f));
            float2 hi = make_float2(fmaxf(c[nt][2] + bx, 0.f),
                                    fmaxf(c[nt][3] + by, 0.f));
            *(float2*)&hs[mbase + lr][j] = lo;
            *(float2*)&hs[mbase + lr + 8][j] = hi;
        }
    }
    __syncthreads();

#pragma unroll
    for (int rnd = 0; rnd < 8; rnd++) {
        int eloc = rnd * 8 + w;
        int e = e0 + eloc;
        int s = esrc[e], d = edst[e];
        const __half* zr = g_Zh + (size_t)s * ZCOLS + lane * 8;
        const float* hr = hs[eloc];
        float msg0 = g_Zb[s * DIM + lane];
        float msg1 = 0.f;
#pragma unroll
        for (int kb = 0; kb < 8; kb += 2) {
            uint4 v0 = __ldg((const uint4*)(zr + kb * 256));
            uint4 v1 = __ldg((const uint4*)(zr + (kb + 1) * 256));
            float4 h0 = *(const float4*)&hr[kb * 8];
            float4 h1 = *(const float4*)&hr[kb * 8 + 4];
            float4 h2 = *(const float4*)&hr[kb * 8 + 8];
            float4 h3 = *(const float4*)&hr[kb * 8 + 12];
            float2 a0 = __half22float2(*(__half2*)&v0.x);
            float2 a1 = __half22float2(*(__half2*)&v0.y);
            float2 a2 = __half22float2(*(__half2*)&v0.z);
            float2 a3 = __half22float2(*(__half2*)&v0.w);
            float2 b0 = __half22float2(*(__half2*)&v1.x);
            float2 b1f = __half22float2(*(__half2*)&v1.y);
            float2 b2f = __half22float2(*(__half2*)&v1.z);
            float2 b3f = __half22float2(*(__half2*)&v1.w);
            msg0 = fmaf(h0.x, a0.x, msg0);
            msg1 = fmaf(h0.y, a0.y, msg1);
            msg0 = fmaf(h0.z, a1.x, msg0);
            msg1 = fmaf(h0.w, a1.y, msg1);
            msg0 = fmaf(h1.x, a2.x, msg0);
            msg1 = fmaf(h1.y, a2.y, msg1);
            msg0 = fmaf(h1.z, a3.x, msg0);
            msg1 = fmaf(h1.w, a3.y, msg1);
            msg0 = fmaf(h2.x, b0.x, msg0);
            msg1 = fmaf(h2.y, b0.y, msg1);
            msg0 = fmaf(h2.z, b1f.x, msg0);
            msg1 = fmaf(h2.w, b1f.y, msg1);
            msg0 = fmaf(h3.x, b2f.x, msg0);
            msg1 = fmaf(h3.y, b2f.y, msg1);
            msg0 = fmaf(h3.z, b3f.x, msg0);
            msg1 = fmaf(h3.w, b3f.y, msg1);
        }
        atomicAdd(&g_agg[d * DIM + lane], msg0 + msg1);
    }
}

// ---------------- K4: node update ----------------
template <bool POOL>
__global__ void k_node_update(const float* __restrict__ xin,
                              const float* __restrict__ root,
                              const float* __restrict__ bias,
                              const float* __restrict__ bng,
                              const float* __restrict__ bnb,
                              const float* __restrict__ bnrm,
                              const float* __restrict__ bnrv,
                              float* __restrict__ xout,
                              const int* __restrict__ batch) {
    __shared__ float Rs[DIM * DIM];
    int t = threadIdx.x;
    for (int i = t; i < DIM * DIM; i += 256) Rs[i] = root[i];
    __syncthreads();
    int n = blockIdx.x * 8 + (t >> 5);
    int o = t & 31;
    const float* xr = xin + (size_t)n * DIM;
    float v = g_agg[n * DIM + o] + bias[o];
#pragma unroll
    for (int i = 0; i < DIM; i++) v = fmaf(xr[i], Rs[i * DIM + o], v);
    v = (v - bnrm[o]) * rsqrtf(bnrv[o] + BN_EPS) * bng[o] + bnb[o];
    v = fmaxf(v, 0.f);
    if (POOL) {
        int b = batch[n];
        atomicMax((int*)&g_pool[b * DIM + o], __float_as_int(v));
    } else {
        xout[n * DIM + o] = v;
    }
}

// ---------------- K6: head ----------------
__global__ void k_head(const float* __restrict__ l1W, const float* __restrict__ l1b,
                       const float* __restrict__ l2W, const float* __restrict__ l2b,
                       float* __restrict__ out) {
    int g = threadIdx.x;
    const float* pr = &g_pool[g * DIM];
    float tbuf[DIM];
#pragma unroll
    for (int j = 0; j < DIM; j++) {
        float v = l1b[j];
#pragma unroll
        for (int i = 0; i < DIM; i++) v = fmaf(pr[i], l1W[i * DIM + j], v);
        tbuf[j] = fmaxf(v, 0.f);
    }
#pragma unroll
    for (int c = 0; c < 2; c++) {
        float v = l2b[c];
#pragma unroll
        for (int j = 0; j < DIM; j++) v = fmaf(tbuf[j], l2W[j * 2 + c], v);
        out[g * 2 + c] = v;
    }
}

// ---------------- launch ----------------
extern "C" void kernel_launch(void* const* d_in, const int* in_sizes, int n_in,
                              void* d_out, int out_size) {
    const float* x     = (const float*)d_in[0];
    const int*   esrc  = (const int*)d_in[1];
    const int*   edst  = (const int*)d_in[2];
    const float* ea    = (const float*)d_in[3];
    const int*   batch = (const int*)d_in[4];

    const float* c0W1 = (const float*)d_in[5];
    const float* c0b1 = (const float*)d_in[6];
    const float* c0W2 = (const float*)d_in[7];
    const float* c0b2 = (const float*)d_in[8];
    const float* c0rt = (const float*)d_in[9];
    const float* c0bs = (const float*)d_in[10];
    const float* bn0g = (const float*)d_in[11];
    const float* bn0b = (const float*)d_in[12];
    const float* bn0m = (const float*)d_in[13];
    const float* bn0v = (const float*)d_in[14];

    const float* c1W1 = (const float*)d_in[15];
    const float* c1b1 = (const float*)d_in[16];
    const float* c1W2 = (const float*)d_in[17];
    const float* c1b2 = (const float*)d_in[18];
    const float* c1rt = (const float*)d_in[19];
    const float* c1bs = (const float*)d_in[20];
    const float* bn1g = (const float*)d_in[21];
    const float* bn1b = (const float*)d_in[22];
    const float* bn1m = (const float*)d_in[23];
    const float* bn1v = (const float*)d_in[24];

    const float* l1W = (const float*)d_in[25];
    const float* l1b = (const float*)d_in[26];
    const float* l2W = (const float*)d_in[27];
    const float* l2b = (const float*)d_in[28];

    float* out = (float*)d_out;

    void* px1 = nullptr;
    cudaGetSymbolAddress(&px1, g_x1);
    float* x1 = (float*)px1;

    dim3 zg(8, (N_NODES + 127) / 128);      // 8 x 157

    // ---- conv0 ----
    k_zero_agg_pool<<<(N_NODES * DIM + 255) / 256, 256>>>();
    k_zgemm<<<zg, 256>>>(x, c0W2);
    k_zb<<<N_NODES / 8, 256>>>(x, c0b2);
    k_edge_fused<<<N_EDGES / EPB, 256>>>(ea, c0W1, c0b1, esrc, edst);
    k_node_update<false><<<N_NODES / 8, 256>>>(x, c0rt, c0bs, bn0g, bn0b,
                                               bn0m, bn0v, x1, nullptr);

    // ---- conv1 ----
    k_zero_agg<<<(N_NODES * DIM + 255) / 256, 256>>>();
    k_zgemm<<<zg, 256>>>(x1, c1W2);
    k_zb<<<N_NODES / 8, 256>>>(x1, c1b2);
    k_edge_fused<<<N_EDGES / EPB, 256>>>(ea, c1W1, c1b1, esrc, edst);
    k_node_update<true><<<N_NODES / 8, 256>>>(x1, c1rt, c1bs, bn1g, bn1b,
                                              bn1m, bn1v, nullptr, batch);

    // ---- head ----
    k_head<<<1, NG>>>(l1W, l1b, l2W, l2b, out);
}

// round 15
// speedup vs baseline: 1.7246x; 1.0369x over previous
#include <cuda_runtime.h>
#include <cuda_fp16.h>
#include <cstdint>

#define N_NODES 20000
#define N_EDGES 160000
#define DIM 32
#define EFD 95
#define EH 64
#define NG 64
#define ZCOLS 2048      // EH * DIM
#define BN_EPS 1e-5f
#define EPB 64          // edges per fused block
#define KP 104          // padded k stride (halves) for eash/W1T
#define HSS 68          // hs row stride (floats)

#define XSP 40          // Xh row stride (halves)
#define BSP 36          // Bh row stride (halves)
#define CSP 72          // Cs row stride (halves)

// ---------------- scratch (device globals) ----------------
__device__ __align__(16) __half g_Zh[(size_t)N_NODES * ZCOLS];  // 82 MB  [n][kb][o][r]
__device__ float  g_Zb[N_NODES * DIM];
__device__ float  g_agg[N_NODES * DIM];
__device__ float  g_x1[N_NODES * DIM];
__device__ float  g_pool[NG * DIM];

// ---------------- zero pool (tiny, once) ----------------
__global__ void k_zero_pool() {
    for (int i = threadIdx.x; i < NG * DIM; i += 256) g_pool[i] = 0.f;
}

// ---------------- mma helper (validated r12/r13) ----------------
__device__ __forceinline__ void mma16816(float* c, const uint32_t* a,
                                         const uint32_t* b) {
    asm volatile(
        "mma.sync.aligned.m16n8k16.row.col.f32.f16.f16.f32 "
        "{%0,%1,%2,%3},{%4,%5,%6,%7},{%8,%9},{%0,%1,%2,%3};\n"
        : "+f"(c[0]), "+f"(c[1]), "+f"(c[2]), "+f"(c[3])
        : "r"(a[0]), "r"(a[1]), "r"(a[2]), "r"(a[3]), "r"(b[0]), "r"(b[1]));
}
__device__ __forceinline__ uint32_t lds_h2(const __half* p) {
    return *(const uint32_t*)p;
}

// ---------------- K2: tensor-core zgemm, 128-node tiles (r14, frozen) -----
__global__ void __launch_bounds__(256) k_zgemm(const float* __restrict__ X,
                                               const float* __restrict__ W2) {
    __shared__ __half Xh[128 * XSP];
    __shared__ __half Bh[256 * BSP];
    __shared__ __half Cs[128 * CSP];
    int t = threadIdx.x;
    int kb = blockIdx.x;
    int n0 = blockIdx.y * 128;

#pragma unroll
    for (int idx = t; idx < 1024; idx += 256) {
        int row = idx >> 3, q = idx & 7;
        int n = n0 + row;
        float4 v = (n < N_NODES) ? *(const float4*)(X + (size_t)n * DIM + q * 4)
                                 : make_float4(0.f, 0.f, 0.f, 0.f);
        __half2 h0 = __floats2half2_rn(v.x, v.y);
        __half2 h1 = __floats2half2_rn(v.z, v.w);
        *(uint32_t*)&Xh[row * XSP + q * 4] = *(uint32_t*)&h0;
        *(uint32_t*)&Xh[row * XSP + q * 4 + 2] = *(uint32_t*)&h1;
    }
    {
        const float* w2src = W2 + (size_t)kb * 8192;
#pragma unroll
        for (int idx = t; idx < 8192; idx += 256) {
            int r = idx >> 10, i = (idx >> 5) & 31, o = idx & 31;
            Bh[(o * 8 + r) * BSP + i] = __float2half(w2src[idx]);
        }
    }
    __syncthreads();

    int lane = t & 31, w = t >> 5;
    int lr = lane >> 2, lc = lane & 3;
    int m0 = w * 16;

    uint32_t a[2][4];
#pragma unroll
    for (int ks = 0; ks < 2; ks++) {
        const __half* ab = &Xh[(m0 + lr) * XSP + ks * 16 + lc * 2];
        a[ks][0] = lds_h2(ab);
        a[ks][1] = lds_h2(ab + 8 * XSP);
        a[ks][2] = lds_h2(ab + 8);
        a[ks][3] = lds_h2(ab + 8 * XSP + 8);
    }

#pragma unroll
    for (int ng = 0; ng < 4; ng++) {
        float c[8][4] = {};
#pragma unroll
        for (int nt = 0; nt < 8; nt++) {
            int j0 = ng * 64 + nt * 8;
#pragma unroll
            for (int ks = 0; ks < 2; ks++) {
                const __half* bb = &Bh[(j0 + lr) * BSP + ks * 16 + lc * 2];
                uint32_t b[2];
                b[0] = lds_h2(bb);
                b[1] = lds_h2(bb + 8);
                mma16816(c[nt], a[ks], b);
            }
        }
        __syncthreads();
#pragma unroll
        for (int nt = 0; nt < 8; nt++) {
            int jj = nt * 8 + lc * 2;
            __half2 lo = __floats2half2_rn(c[nt][0], c[nt][1]);
            __half2 hi = __floats2half2_rn(c[nt][2], c[nt][3]);
            *(uint32_t*)&Cs[(m0 + lr) * CSP + jj] = *(uint32_t*)&lo;
            *(uint32_t*)&Cs[(m0 + lr + 8) * CSP + jj] = *(uint32_t*)&hi;
        }
        __syncthreads();
#pragma unroll
        for (int idx = t; idx < 1024; idx += 256) {
            int row = idx >> 3, seg = idx & 7;
            int n = n0 + row;
            if (n < N_NODES)
                *(uint4*)&g_Zh[(size_t)n * ZCOLS + kb * 256 + ng * 64 + seg * 8] =
                    *(const uint4*)&Cs[row * CSP + seg * 8];
        }
    }
}

// ---------------- K2b: Zb + agg zeroing (fused) ----------------
__global__ void k_zb(const float* __restrict__ X, const float* __restrict__ b2) {
    __shared__ float Bs[DIM * DIM];
    int t = threadIdx.x;
    for (int i = t; i < DIM * DIM; i += 256) Bs[i] = b2[i];
    __syncthreads();
    int n = blockIdx.x * 8 + (t >> 5);
    int o = t & 31;
    const float* xr = X + (size_t)n * DIM;
    float v = 0.f;
#pragma unroll
    for (int i = 0; i < DIM; i++) v = fmaf(xr[i], Bs[i * DIM + o], v);
    g_Zb[n * DIM + o] = v;
    g_agg[n * DIM + o] = 0.f;       // agg zeroing folded here
}

// ---------------- K3: FUSED edge MLP (HMMA) + scatter (r13/r14, frozen) ---
__global__ void __launch_bounds__(256) k_edge_fused(const float* __restrict__ ea,
                                                    const float* __restrict__ W1,
                                                    const float* __restrict__ b1,
                                                    const int* __restrict__ esrc,
                                                    const int* __restrict__ edst) {
    __shared__ __half eash[EPB * KP];
    __shared__ __half W1T[EH * KP];
    __shared__ float  hs[EPB][HSS];
    int t = threadIdx.x;
    int e0 = blockIdx.x * EPB;

    for (int idx = t; idx < EPB * 96; idx += 256) {
        int el = idx / 96, k = idx - el * 96;
        eash[el * KP + k] = (k < EFD)
            ? __float2half(ea[(size_t)(e0 + el) * EFD + k]) : __half(0.f);
    }
    for (int idx = t; idx < EH * 96; idx += 256) {
        int k = idx >> 6, j = idx & 63;
        W1T[j * KP + k] = (k < EFD) ? __float2half(W1[k * EH + j]) : __half(0.f);
    }
    __syncthreads();

    int lane = t & 31, w = t >> 5;
    int lr = lane >> 2, lc = lane & 3;

    {
        int mbase = (w & 3) * 16;
        int jbase = (w >> 2) * 32;
        float c[4][4] = {};
#pragma unroll
        for (int ks = 0; ks < 6; ks++) {
            const __half* ab = &eash[(mbase + lr) * KP + ks * 16 + lc * 2];
            uint32_t a[4];
            a[0] = lds_h2(ab);
            a[1] = lds_h2(ab + 8 * KP);
            a[2] = lds_h2(ab + 8);
            a[3] = lds_h2(ab + 8 * KP + 8);
#pragma unroll
            for (int nt = 0; nt < 4; nt++) {
                const __half* bb = &W1T[(jbase + nt * 8 + lr) * KP + ks * 16 + lc * 2];
                uint32_t b[2];
                b[0] = lds_h2(bb);
                b[1] = lds_h2(bb + 8);
                mma16816(c[nt], a, b);
            }
        }
#pragma unroll
        for (int nt = 0; nt < 4; nt++) {
            int j = jbase + nt * 8 + lc * 2;
            float bx = b1[j], by = b1[j + 1];
            float2 lo = make_float2(fmaxf(c[nt][0] + bx, 0.f),
                                    fmaxf(c[nt][1] + by, 0.f));
            float2 hi = make_float2(fmaxf(c[nt][2] + bx, 0.f),
                                    fmaxf(c[nt][3] + by, 0.f));
            *(float2*)&hs[mbase + lr][j] = lo;
            *(float2*)&hs[mbase + lr + 8][j] = hi;
        }
    }
    __syncthreads();

#pragma unroll
    for (int rnd = 0; rnd < 8; rnd++) {
        int eloc = rnd * 8 + w;
        int e = e0 + eloc;
        int s = esrc[e], d = edst[e];
        const __half* zr = g_Zh + (size_t)s * ZCOLS + lane * 8;
        const float* hr = hs[eloc];
        float msg0 = g_Zb[s * DIM + lane];
        float msg1 = 0.f;
#pragma unroll
        for (int kb = 0; kb < 8; kb += 2) {
            uint4 v0 = __ldg((const uint4*)(zr + kb * 256));
            uint4 v1 = __ldg((const uint4*)(zr + (kb + 1) * 256));
            float4 h0 = *(const float4*)&hr[kb * 8];
            float4 h1 = *(const float4*)&hr[kb * 8 + 4];
            float4 h2 = *(const float4*)&hr[kb * 8 + 8];
            float4 h3 = *(const float4*)&hr[kb * 8 + 12];
            float2 a0 = __half22float2(*(__half2*)&v0.x);
            float2 a1 = __half22float2(*(__half2*)&v0.y);
            float2 a2 = __half22float2(*(__half2*)&v0.z);
            float2 a3 = __half22float2(*(__half2*)&v0.w);
            float2 b0 = __half22float2(*(__half2*)&v1.x);
            float2 b1f = __half22float2(*(__half2*)&v1.y);
            float2 b2f = __half22float2(*(__half2*)&v1.z);
            float2 b3f = __half22float2(*(__half2*)&v1.w);
            msg0 = fmaf(h0.x, a0.x, msg0);
            msg1 = fmaf(h0.y, a0.y, msg1);
            msg0 = fmaf(h0.z, a1.x, msg0);
            msg1 = fmaf(h0.w, a1.y, msg1);
            msg0 = fmaf(h1.x, a2.x, msg0);
            msg1 = fmaf(h1.y, a2.y, msg1);
            msg0 = fmaf(h1.z, a3.x, msg0);
            msg1 = fmaf(h1.w, a3.y, msg1);
            msg0 = fmaf(h2.x, b0.x, msg0);
            msg1 = fmaf(h2.y, b0.y, msg1);
            msg0 = fmaf(h2.z, b1f.x, msg0);
            msg1 = fmaf(h2.w, b1f.y, msg1);
            msg0 = fmaf(h3.x, b2f.x, msg0);
            msg1 = fmaf(h3.y, b2f.y, msg1);
            msg0 = fmaf(h3.z, b3f.x, msg0);
            msg1 = fmaf(h3.w, b3f.y, msg1);
        }
        atomicAdd(&g_agg[d * DIM + lane], msg0 + msg1);
    }
}

// ---------------- K4: node update, 32 nodes/block ----------------
template <bool POOL>
__global__ void __launch_bounds__(256) k_node_update(
        const float* __restrict__ xin,
        const float* __restrict__ root,
        const float* __restrict__ bias,
        const float* __restrict__ bng,
        const float* __restrict__ bnb,
        const float* __restrict__ bnrm,
        const float* __restrict__ bnrv,
        float* __restrict__ xout,
        const int* __restrict__ batch) {
    __shared__ float Rs[DIM * DIM];
    int t = threadIdx.x;
    for (int i = t; i < DIM * DIM; i += 256) Rs[i] = root[i];
    __syncthreads();
    int o = t & 31;
    int nb = blockIdx.x * 32 + (t >> 5) * 4;
    float bs = bias[o];
    float sc = rsqrtf(bnrv[o] + BN_EPS) * bng[o];
    float rm = bnrm[o], bb = bnb[o];
#pragma unroll
    for (int r = 0; r < 4; r++) {
        int n = nb + r;
        const float* xr = xin + (size_t)n * DIM;
        float v = g_agg[n * DIM + o] + bs;
#pragma unroll
        for (int i = 0; i < DIM; i++) v = fmaf(xr[i], Rs[i * DIM + o], v);
        v = (v - rm) * sc + bb;
        v = fmaxf(v, 0.f);
        if (POOL) {
            int b = batch[n];
            atomicMax((int*)&g_pool[b * DIM + o], __float_as_int(v));
        } else {
            xout[n * DIM + o] = v;
        }
    }
}

// ---------------- K6: head ----------------
__global__ void k_head(const float* __restrict__ l1W, const float* __restrict__ l1b,
                       const float* __restrict__ l2W, const float* __restrict__ l2b,
                       float* __restrict__ out) {
    int g = threadIdx.x;
    const float* pr = &g_pool[g * DIM];
    float tbuf[DIM];
#pragma unroll
    for (int j = 0; j < DIM; j++) {
        float v = l1b[j];
#pragma unroll
        for (int i = 0; i < DIM; i++) v = fmaf(pr[i], l1W[i * DIM + j], v);
        tbuf[j] = fmaxf(v, 0.f);
    }
#pragma unroll
    for (int c = 0; c < 2; c++) {
        float v = l2b[c];
#pragma unroll
        for (int j = 0; j < DIM; j++) v = fmaf(tbuf[j], l2W[j * 2 + c], v);
        out[g * 2 + c] = v;
    }
}

// ---------------- launch ----------------
extern "C" void kernel_launch(void* const* d_in, const int* in_sizes, int n_in,
                              void* d_out, int out_size) {
    const float* x     = (const float*)d_in[0];
    const int*   esrc  = (const int*)d_in[1];
    const int*   edst  = (const int*)d_in[2];
    const float* ea    = (const float*)d_in[3];
    const int*   batch = (const int*)d_in[4];

    const float* c0W1 = (const float*)d_in[5];
    const float* c0b1 = (const float*)d_in[6];
    const float* c0W2 = (const float*)d_in[7];
    const float* c0b2 = (const float*)d_in[8];
    const float* c0rt = (const float*)d_in[9];
    const float* c0bs = (const float*)d_in[10];
    const float* bn0g = (const float*)d_in[11];
    const float* bn0b = (const float*)d_in[12];
    const float* bn0m = (const float*)d_in[13];
    const float* bn0v = (const float*)d_in[14];

    const float* c1W1 = (const float*)d_in[15];
    const float* c1b1 = (const float*)d_in[16];
    const float* c1W2 = (const float*)d_in[17];
    const float* c1b2 = (const float*)d_in[18];
    const float* c1rt = (const float*)d_in[19];
    const float* c1bs = (const float*)d_in[20];
    const float* bn1g = (const float*)d_in[21];
    const float* bn1b = (const float*)d_in[22];
    const float* bn1m = (const float*)d_in[23];
    const float* bn1v = (const float*)d_in[24];

    const float* l1W = (const float*)d_in[25];
    const float* l1b = (const float*)d_in[26];
    const float* l2W = (const float*)d_in[27];
    const float* l2b = (const float*)d_in[28];

    float* out = (float*)d_out;

    void* px1 = nullptr;
    cudaGetSymbolAddress(&px1, g_x1);
    float* x1 = (float*)px1;

    dim3 zg(8, (N_NODES + 127) / 128);      // 8 x 157

    // ---- conv0 ----
    k_zero_pool<<<1, 256>>>();
    k_zgemm<<<zg, 256>>>(x, c0W2);
    k_zb<<<N_NODES / 8, 256>>>(x, c0b2);    // also zeroes g_agg
    k_edge_fused<<<N_EDGES / EPB, 256>>>(ea, c0W1, c0b1, esrc, edst);
    k_node_update<false><<<N_NODES / 32, 256>>>(x, c0rt, c0bs, bn0g, bn0b,
                                                bn0m, bn0v, x1, nullptr);

    // ---- conv1 ----
    k_zgemm<<<zg, 256>>>(x1, c1W2);
    k_zb<<<N_NODES / 8, 256>>>(x1, c1b2);   // also zeroes g_agg
    k_edge_fused<<<N_EDGES / EPB, 256>>>(ea, c1W1, c1b1, esrc, edst);
    k_node_update<true><<<N_NODES / 32, 256>>>(x1, c1rt, c1bs, bn1g, bn1b,
                                               bn1m, bn1v, nullptr, batch);

    // ---- head ----
    k_head<<<1, NG>>>(l1W, l1b, l2W, l2b, out);
}

// round 16
// speedup vs baseline: 1.8558x; 1.0761x over previous
#include <cuda_runtime.h>
#include <cuda_fp16.h>
#include <cstdint>

#define N_NODES 20000
#define N_EDGES 160000
#define DIM 32
#define EFD 95
#define EH 64
#define NG 64
#define ZCOLS 2048      // EH * DIM
#define BN_EPS 1e-5f
#define EPB 64          // edges per fused block
#define KP 104          // padded k stride (halves) for eash/W1T
#define HSP 72          // hs row stride (halves), 144B rows (16B aligned)

#define XSP 40          // Xh row stride (halves)
#define BSP 36          // Bh row stride (halves)
#define CSP 72          // Cs row stride (halves)

// ---------------- scratch (device globals) ----------------
__device__ __align__(16) __half g_Zh[(size_t)N_NODES * ZCOLS];  // 82 MB
__device__ __align__(16) __half g_eah[(size_t)N_EDGES * 96];    // 30.7 MB fp16 ea, padded
__device__ float  g_Zb[N_NODES * DIM];
__device__ float  g_agg[N_NODES * DIM];
__device__ float  g_x1[N_NODES * DIM];
__device__ float  g_pool[NG * DIM];

// ---------------- zero pool (tiny, once) ----------------
__global__ void k_zero_pool() {
    for (int i = threadIdx.x; i < NG * DIM; i += 256) g_pool[i] = 0.f;
}

// ---------------- ea -> fp16 padded converter (once) ----------------
__global__ void __launch_bounds__(256) k_ea2h(const float* __restrict__ ea) {
    int e0 = blockIdx.x * 32;
#pragma unroll
    for (int idx = threadIdx.x; idx < 32 * 96; idx += 256) {
        int el = idx / 96, k = idx - el * 96;
        float v = (k < EFD) ? ea[(size_t)(e0 + el) * EFD + k] : 0.f;
        g_eah[(size_t)(e0 + el) * 96 + k] = __float2half(v);
    }
}

// ---------------- mma helper (validated r12/r13) ----------------
__device__ __forceinline__ void mma16816(float* c, const uint32_t* a,
                                         const uint32_t* b) {
    asm volatile(
        "mma.sync.aligned.m16n8k16.row.col.f32.f16.f16.f32 "
        "{%0,%1,%2,%3},{%4,%5,%6,%7},{%8,%9},{%0,%1,%2,%3};\n"
        : "+f"(c[0]), "+f"(c[1]), "+f"(c[2]), "+f"(c[3])
        : "r"(a[0]), "r"(a[1]), "r"(a[2]), "r"(a[3]), "r"(b[0]), "r"(b[1]));
}
__device__ __forceinline__ uint32_t lds_h2(const __half* p) {
    return *(const uint32_t*)p;
}

// ---------------- K2: tensor-core zgemm, 128-node tiles (frozen) ----------
__global__ void __launch_bounds__(256) k_zgemm(const float* __restrict__ X,
                                               const float* __restrict__ W2) {
    __shared__ __half Xh[128 * XSP];
    __shared__ __half Bh[256 * BSP];
    __shared__ __half Cs[128 * CSP];
    int t = threadIdx.x;
    int kb = blockIdx.x;
    int n0 = blockIdx.y * 128;

#pragma unroll
    for (int idx = t; idx < 1024; idx += 256) {
        int row = idx >> 3, q = idx & 7;
        int n = n0 + row;
        float4 v = (n < N_NODES) ? *(const float4*)(X + (size_t)n * DIM + q * 4)
                                 : make_float4(0.f, 0.f, 0.f, 0.f);
        __half2 h0 = __floats2half2_rn(v.x, v.y);
        __half2 h1 = __floats2half2_rn(v.z, v.w);
        *(uint32_t*)&Xh[row * XSP + q * 4] = *(uint32_t*)&h0;
        *(uint32_t*)&Xh[row * XSP + q * 4 + 2] = *(uint32_t*)&h1;
    }
    {
        const float* w2src = W2 + (size_t)kb * 8192;
#pragma unroll
        for (int idx = t; idx < 8192; idx += 256) {
            int r = idx >> 10, i = (idx >> 5) & 31, o = idx & 31;
            Bh[(o * 8 + r) * BSP + i] = __float2half(w2src[idx]);
        }
    }
    __syncthreads();

    int lane = t & 31, w = t >> 5;
    int lr = lane >> 2, lc = lane & 3;
    int m0 = w * 16;

    uint32_t a[2][4];
#pragma unroll
    for (int ks = 0; ks < 2; ks++) {
        const __half* ab = &Xh[(m0 + lr) * XSP + ks * 16 + lc * 2];
        a[ks][0] = lds_h2(ab);
        a[ks][1] = lds_h2(ab + 8 * XSP);
        a[ks][2] = lds_h2(ab + 8);
        a[ks][3] = lds_h2(ab + 8 * XSP + 8);
    }

#pragma unroll
    for (int ng = 0; ng < 4; ng++) {
        float c[8][4] = {};
#pragma unroll
        for (int nt = 0; nt < 8; nt++) {
            int j0 = ng * 64 + nt * 8;
#pragma unroll
            for (int ks = 0; ks < 2; ks++) {
                const __half* bb = &Bh[(j0 + lr) * BSP + ks * 16 + lc * 2];
                uint32_t b[2];
                b[0] = lds_h2(bb);
                b[1] = lds_h2(bb + 8);
                mma16816(c[nt], a[ks], b);
            }
        }
        __syncthreads();
#pragma unroll
        for (int nt = 0; nt < 8; nt++) {
            int jj = nt * 8 + lc * 2;
            __half2 lo = __floats2half2_rn(c[nt][0], c[nt][1]);
            __half2 hi = __floats2half2_rn(c[nt][2], c[nt][3]);
            *(uint32_t*)&Cs[(m0 + lr) * CSP + jj] = *(uint32_t*)&lo;
            *(uint32_t*)&Cs[(m0 + lr + 8) * CSP + jj] = *(uint32_t*)&hi;
        }
        __syncthreads();
#pragma unroll
        for (int idx = t; idx < 1024; idx += 256) {
            int row = idx >> 3, seg = idx & 7;
            int n = n0 + row;
            if (n < N_NODES)
                *(uint4*)&g_Zh[(size_t)n * ZCOLS + kb * 256 + ng * 64 + seg * 8] =
                    *(const uint4*)&Cs[row * CSP + seg * 8];
        }
    }
}

// ---------------- K2b: Zb + agg zeroing (fused) ----------------
__global__ void k_zb(const float* __restrict__ X, const float* __restrict__ b2) {
    __shared__ float Bs[DIM * DIM];
    int t = threadIdx.x;
    for (int i = t; i < DIM * DIM; i += 256) Bs[i] = b2[i];
    __syncthreads();
    int n = blockIdx.x * 8 + (t >> 5);
    int o = t & 31;
    const float* xr = X + (size_t)n * DIM;
    float v = 0.f;
#pragma unroll
    for (int i = 0; i < DIM; i++) v = fmaf(xr[i], Bs[i * DIM + o], v);
    g_Zb[n * DIM + o] = v;
    g_agg[n * DIM + o] = 0.f;
}

// ---------------- K3: FUSED edge MLP (HMMA) + scatter ----------------
// eash filled by uint4 copies from pre-converted g_eah; hs stored fp16.
__global__ void __launch_bounds__(256) k_edge_fused(const float* __restrict__ W1,
                                                    const float* __restrict__ b1,
                                                    const int* __restrict__ esrc,
                                                    const int* __restrict__ edst) {
    __shared__ __half eash[EPB * KP];       // 13312 B
    __shared__ __half W1T[EH * KP];         // 13312 B
    __shared__ __half hs[EPB * HSP];        // 9216 B  (~36 KB total)
    int t = threadIdx.x;
    int e0 = blockIdx.x * EPB;

    // eash fill: 64 rows x 12 uint4 (96 halves), dst stride 13 uint4 (104 halves)
    {
        const uint4* src = (const uint4*)(g_eah + (size_t)e0 * 96);
        uint4* dst = (uint4*)eash;
#pragma unroll
        for (int idx = t; idx < EPB * 12; idx += 256) {
            int row = idx / 12, q = idx - row * 12;
            dst[row * 13 + q] = src[idx];
        }
        // zero pad halves 96..103 of each row (frag loads read k<96 only, but keep clean)
    }
    for (int idx = t; idx < EH * 96; idx += 256) {
        int k = idx >> 6, j = idx & 63;
        W1T[j * KP + k] = (k < EFD) ? __float2half(W1[k * EH + j]) : __half(0.f);
    }
    __syncthreads();

    int lane = t & 31, w = t >> 5;
    int lr = lane >> 2, lc = lane & 3;

    // ---- phase 1: HMMA edge MLP ----
    {
        int mbase = (w & 3) * 16;
        int jbase = (w >> 2) * 32;
        float c[4][4] = {};
#pragma unroll
        for (int ks = 0; ks < 6; ks++) {
            const __half* ab = &eash[(mbase + lr) * KP + ks * 16 + lc * 2];
            uint32_t a[4];
            a[0] = lds_h2(ab);
            a[1] = lds_h2(ab + 8 * KP);
            a[2] = lds_h2(ab + 8);
            a[3] = lds_h2(ab + 8 * KP + 8);
#pragma unroll
            for (int nt = 0; nt < 4; nt++) {
                const __half* bb = &W1T[(jbase + nt * 8 + lr) * KP + ks * 16 + lc * 2];
                uint32_t b[2];
                b[0] = lds_h2(bb);
                b[1] = lds_h2(bb + 8);
                mma16816(c[nt], a, b);
            }
        }
        // epilogue: +bias, relu, -> hs (fp16)
#pragma unroll
        for (int nt = 0; nt < 4; nt++) {
            int j = jbase + nt * 8 + lc * 2;
            float bx = b1[j], by = b1[j + 1];
            __half2 lo = __floats2half2_rn(fmaxf(c[nt][0] + bx, 0.f),
                                           fmaxf(c[nt][1] + by, 0.f));
            __half2 hi = __floats2half2_rn(fmaxf(c[nt][2] + bx, 0.f),
                                           fmaxf(c[nt][3] + by, 0.f));
            *(uint32_t*)&hs[(mbase + lr) * HSP + j] = *(uint32_t*)&lo;
            *(uint32_t*)&hs[(mbase + lr + 8) * HSP + j] = *(uint32_t*)&hi;
        }
    }
    __syncthreads();

    // ---- phase 2: scatter (warp per edge, 8 rounds) ----
#pragma unroll
    for (int rnd = 0; rnd < 8; rnd++) {
        int eloc = rnd * 8 + w;
        int e = e0 + eloc;
        int s = esrc[e], d = edst[e];
        const __half* zr = g_Zh + (size_t)s * ZCOLS + lane * 8;
        const __half* hr = &hs[eloc * HSP];
        float msg0 = g_Zb[s * DIM + lane];
        float msg1 = 0.f;
#pragma unroll
        for (int kb = 0; kb < 8; kb += 2) {
            uint4 v0 = __ldg((const uint4*)(zr + kb * 256));
            uint4 v1 = __ldg((const uint4*)(zr + (kb + 1) * 256));
            uint4 hh0 = *(const uint4*)(hr + kb * 8);       // broadcast LDS.128
            uint4 hh1 = *(const uint4*)(hr + kb * 8 + 8);   // broadcast LDS.128
            float2 h0 = __half22float2(*(__half2*)&hh0.x);
            float2 h1 = __half22float2(*(__half2*)&hh0.y);
            float2 h2 = __half22float2(*(__half2*)&hh0.z);
            float2 h3 = __half22float2(*(__half2*)&hh0.w);
            float2 h4 = __half22float2(*(__half2*)&hh1.x);
            float2 h5 = __half22float2(*(__half2*)&hh1.y);
            float2 h6 = __half22float2(*(__half2*)&hh1.z);
            float2 h7 = __half22float2(*(__half2*)&hh1.w);
            float2 a0 = __half22float2(*(__half2*)&v0.x);
            float2 a1 = __half22float2(*(__half2*)&v0.y);
            float2 a2 = __half22float2(*(__half2*)&v0.z);
            float2 a3 = __half22float2(*(__half2*)&v0.w);
            float2 b0 = __half22float2(*(__half2*)&v1.x);
            float2 b1f = __half22float2(*(__half2*)&v1.y);
            float2 b2f = __half22float2(*(__half2*)&v1.z);
            float2 b3f = __half22float2(*(__half2*)&v1.w);
            msg0 = fmaf(h0.x, a0.x, msg0);
            msg1 = fmaf(h0.y, a0.y, msg1);
            msg0 = fmaf(h1.x, a1.x, msg0);
            msg1 = fmaf(h1.y, a1.y, msg1);
            msg0 = fmaf(h2.x, a2.x, msg0);
            msg1 = fmaf(h2.y, a2.y, msg1);
            msg0 = fmaf(h3.x, a3.x, msg0);
            msg1 = fmaf(h3.y, a3.y, msg1);
            msg0 = fmaf(h4.x, b0.x, msg0);
            msg1 = fmaf(h4.y, b0.y, msg1);
            msg0 = fmaf(h5.x, b1f.x, msg0);
            msg1 = fmaf(h5.y, b1f.y, msg1);
            msg0 = fmaf(h6.x, b2f.x, msg0);
            msg1 = fmaf(h6.y, b2f.y, msg1);
            msg0 = fmaf(h7.x, b3f.x, msg0);
            msg1 = fmaf(h7.y, b3f.y, msg1);
        }
        atomicAdd(&g_agg[d * DIM + lane], msg0 + msg1);
    }
}

// ---------------- K4: node update, 32 nodes/block (frozen) ----------------
template <bool POOL>
__global__ void __launch_bounds__(256) k_node_update(
        const float* __restrict__ xin,
        const float* __restrict__ root,
        const float* __restrict__ bias,
        const float* __restrict__ bng,
        const float* __restrict__ bnb,
        const float* __restrict__ bnrm,
        const float* __restrict__ bnrv,
        float* __restrict__ xout,
        const int* __restrict__ batch) {
    __shared__ float Rs[DIM * DIM];
    int t = threadIdx.x;
    for (int i = t; i < DIM * DIM; i += 256) Rs[i] = root[i];
    __syncthreads();
    int o = t & 31;
    int nb = blockIdx.x * 32 + (t >> 5) * 4;
    float bs = bias[o];
    float sc = rsqrtf(bnrv[o] + BN_EPS) * bng[o];
    float rm = bnrm[o], bb = bnb[o];
#pragma unroll
    for (int r = 0; r < 4; r++) {
        int n = nb + r;
        const float* xr = xin + (size_t)n * DIM;
        float v = g_agg[n * DIM + o] + bs;
#pragma unroll
        for (int i = 0; i < DIM; i++) v = fmaf(xr[i], Rs[i * DIM + o], v);
        v = (v - rm) * sc + bb;
        v = fmaxf(v, 0.f);
        if (POOL) {
            int b = batch[n];
            atomicMax((int*)&g_pool[b * DIM + o], __float_as_int(v));
        } else {
            xout[n * DIM + o] = v;
        }
    }
}

// ---------------- K6: head ----------------
__global__ void k_head(const float* __restrict__ l1W, const float* __restrict__ l1b,
                       const float* __restrict__ l2W, const float* __restrict__ l2b,
                       float* __restrict__ out) {
    int g = threadIdx.x;
    const float* pr = &g_pool[g * DIM];
    float tbuf[DIM];
#pragma unroll
    for (int j = 0; j < DIM; j++) {
        float v = l1b[j];
#pragma unroll
        for (int i = 0; i < DIM; i++) v = fmaf(pr[i], l1W[i * DIM + j], v);
        tbuf[j] = fmaxf(v, 0.f);
    }
#pragma unroll
    for (int c = 0; c < 2; c++) {
        float v = l2b[c];
#pragma unroll
        for (int j = 0; j < DIM; j++) v = fmaf(tbuf[j], l2W[j * 2 + c], v);
        out[g * 2 + c] = v;
    }
}

// ---------------- launch ----------------
extern "C" void kernel_launch(void* const* d_in, const int* in_sizes, int n_in,
                              void* d_out, int out_size) {
    const float* x     = (const float*)d_in[0];
    const int*   esrc  = (const int*)d_in[1];
    const int*   edst  = (const int*)d_in[2];
    const float* ea    = (const float*)d_in[3];
    const int*   batch = (const int*)d_in[4];

    const float* c0W1 = (const float*)d_in[5];
    const float* c0b1 = (const float*)d_in[6];
    const float* c0W2 = (const float*)d_in[7];
    const float* c0b2 = (const float*)d_in[8];
    const float* c0rt = (const float*)d_in[9];
    const float* c0bs = (const float*)d_in[10];
    const float* bn0g = (const float*)d_in[11];
    const float* bn0b = (const float*)d_in[12];
    const float* bn0m = (const float*)d_in[13];
    const float* bn0v = (const float*)d_in[14];

    const float* c1W1 = (const float*)d_in[15];
    const float* c1b1 = (const float*)d_in[16];
    const float* c1W2 = (const float*)d_in[17];
    const float* c1b2 = (const float*)d_in[18];
    const float* c1rt = (const float*)d_in[19];
    const float* c1bs = (const float*)d_in[20];
    const float* bn1g = (const float*)d_in[21];
    const float* bn1b = (const float*)d_in[22];
    const float* bn1m = (const float*)d_in[23];
    const float* bn1v = (const float*)d_in[24];

    const float* l1W = (const float*)d_in[25];
    const float* l1b = (const float*)d_in[26];
    const float* l2W = (const float*)d_in[27];
    const float* l2b = (const float*)d_in[28];

    float* out = (float*)d_out;

    void* px1 = nullptr;
    cudaGetSymbolAddress(&px1, g_x1);
    float* x1 = (float*)px1;

    dim3 zg(8, (N_NODES + 127) / 128);      // 8 x 157

    // ---- prep ----
    k_zero_pool<<<1, 256>>>();
    k_ea2h<<<N_EDGES / 32, 256>>>(ea);

    // ---- conv0 ----
    k_zgemm<<<zg, 256>>>(x, c0W2);
    k_zb<<<N_NODES / 8, 256>>>(x, c0b2);    // also zeroes g_agg
    k_edge_fused<<<N_EDGES / EPB, 256>>>(c0W1, c0b1, esrc, edst);
    k_node_update<false><<<N_NODES / 32, 256>>>(x, c0rt, c0bs, bn0g, bn0b,
                                                bn0m, bn0v, x1, nullptr);

    // ---- conv1 ----
    k_zgemm<<<zg, 256>>>(x1, c1W2);
    k_zb<<<N_NODES / 8, 256>>>(x1, c1b2);   // also zeroes g_agg
    k_edge_fused<<<N_EDGES / EPB, 256>>>(c1W1, c1b1, esrc, edst);
    k_node_update<true><<<N_NODES / 32, 256>>>(x1, c1rt, c1bs, bn1g, bn1b,
                                               bn1m, bn1v, nullptr, batch);

    // ---- head ----
    k_head<<<1, NG>>>(l1W, l1b, l2W, l2b, out);
}

// round 17
// speedup vs baseline: 1.8771x; 1.0115x over previous
#include <cuda_runtime.h>
#include <cuda_fp16.h>
#include <cstdint>

#define N_NODES 20000
#define N_EDGES 160000
#define DIM 32
#define EFD 95
#define EH 64
#define NG 64
#define ZCOLS 2048      // EH * DIM
#define BN_EPS 1e-5f
#define EPB 64          // edges per fused block
#define KP 104          // padded k stride (halves) for eash/W1T
#define HSP 72          // hs row stride (halves)

#define XSP 40          // Xh row stride (halves)
#define BSP 36          // Bh row stride (halves)
#define CSP 72          // Cs row stride (halves)

// ---------------- scratch (device globals) ----------------
__device__ __align__(16) __half g_Zh[(size_t)N_NODES * ZCOLS];  // 82 MB
__device__ __align__(16) __half g_eah[(size_t)N_EDGES * 96];    // 30.7 MB
__device__ float  g_Zb[N_NODES * DIM];
__device__ float  g_agg[N_NODES * DIM];
__device__ float  g_x1[N_NODES * DIM];
__device__ float  g_pool[NG * DIM];

// ---------------- ea -> fp16 padded converter (+pool zero, once) ----------
__global__ void __launch_bounds__(256) k_ea2h(const float* __restrict__ ea) {
    if (blockIdx.x == 0) {
        for (int i = threadIdx.x; i < NG * DIM; i += 256) g_pool[i] = 0.f;
    }
    int e0 = blockIdx.x * 32;
#pragma unroll
    for (int idx = threadIdx.x; idx < 32 * 96; idx += 256) {
        int el = idx / 96, k = idx - el * 96;
        float v = (k < EFD) ? ea[(size_t)(e0 + el) * EFD + k] : 0.f;
        g_eah[(size_t)(e0 + el) * 96 + k] = __float2half(v);
    }
}

// ---------------- mma helper (validated r12/r13) ----------------
__device__ __forceinline__ void mma16816(float* c, const uint32_t* a,
                                         const uint32_t* b) {
    asm volatile(
        "mma.sync.aligned.m16n8k16.row.col.f32.f16.f16.f32 "
        "{%0,%1,%2,%3},{%4,%5,%6,%7},{%8,%9},{%0,%1,%2,%3};\n"
        : "+f"(c[0]), "+f"(c[1]), "+f"(c[2]), "+f"(c[3])
        : "r"(a[0]), "r"(a[1]), "r"(a[2]), "r"(a[3]), "r"(b[0]), "r"(b[1]));
}
__device__ __forceinline__ uint32_t lds_h2(const __half* p) {
    return *(const uint32_t*)p;
}

// ---------------- K2: tensor-core zgemm, 128-node tiles (frozen) ----------
__global__ void __launch_bounds__(256) k_zgemm(const float* __restrict__ X,
                                               const float* __restrict__ W2) {
    __shared__ __half Xh[128 * XSP];
    __shared__ __half Bh[256 * BSP];
    __shared__ __half Cs[128 * CSP];
    int t = threadIdx.x;
    int kb = blockIdx.x;
    int n0 = blockIdx.y * 128;

#pragma unroll
    for (int idx = t; idx < 1024; idx += 256) {
        int row = idx >> 3, q = idx & 7;
        int n = n0 + row;
        float4 v = (n < N_NODES) ? *(const float4*)(X + (size_t)n * DIM + q * 4)
                                 : make_float4(0.f, 0.f, 0.f, 0.f);
        __half2 h0 = __floats2half2_rn(v.x, v.y);
        __half2 h1 = __floats2half2_rn(v.z, v.w);
        *(uint32_t*)&Xh[row * XSP + q * 4] = *(uint32_t*)&h0;
        *(uint32_t*)&Xh[row * XSP + q * 4 + 2] = *(uint32_t*)&h1;
    }
    {
        const float* w2src = W2 + (size_t)kb * 8192;
#pragma unroll
        for (int idx = t; idx < 8192; idx += 256) {
            int r = idx >> 10, i = (idx >> 5) & 31, o = idx & 31;
            Bh[(o * 8 + r) * BSP + i] = __float2half(w2src[idx]);
        }
    }
    __syncthreads();

    int lane = t & 31, w = t >> 5;
    int lr = lane >> 2, lc = lane & 3;
    int m0 = w * 16;

    uint32_t a[2][4];
#pragma unroll
    for (int ks = 0; ks < 2; ks++) {
        const __half* ab = &Xh[(m0 + lr) * XSP + ks * 16 + lc * 2];
        a[ks][0] = lds_h2(ab);
        a[ks][1] = lds_h2(ab + 8 * XSP);
        a[ks][2] = lds_h2(ab + 8);
        a[ks][3] = lds_h2(ab + 8 * XSP + 8);
    }

#pragma unroll
    for (int ng = 0; ng < 4; ng++) {
        float c[8][4] = {};
#pragma unroll
        for (int nt = 0; nt < 8; nt++) {
            int j0 = ng * 64 + nt * 8;
#pragma unroll
            for (int ks = 0; ks < 2; ks++) {
                const __half* bb = &Bh[(j0 + lr) * BSP + ks * 16 + lc * 2];
                uint32_t b[2];
                b[0] = lds_h2(bb);
                b[1] = lds_h2(bb + 8);
                mma16816(c[nt], a[ks], b);
            }
        }
        __syncthreads();
#pragma unroll
        for (int nt = 0; nt < 8; nt++) {
            int jj = nt * 8 + lc * 2;
            __half2 lo = __floats2half2_rn(c[nt][0], c[nt][1]);
            __half2 hi = __floats2half2_rn(c[nt][2], c[nt][3]);
            *(uint32_t*)&Cs[(m0 + lr) * CSP + jj] = *(uint32_t*)&lo;
            *(uint32_t*)&Cs[(m0 + lr + 8) * CSP + jj] = *(uint32_t*)&hi;
        }
        __syncthreads();
#pragma unroll
        for (int idx = t; idx < 1024; idx += 256) {
            int row = idx >> 3, seg = idx & 7;
            int n = n0 + row;
            if (n < N_NODES)
                *(uint4*)&g_Zh[(size_t)n * ZCOLS + kb * 256 + ng * 64 + seg * 8] =
                    *(const uint4*)&Cs[row * CSP + seg * 8];
        }
    }
}

// ---------------- K2b: Zb + agg zeroing, 32 nodes/block ----------------
__global__ void __launch_bounds__(256) k_zb(const float* __restrict__ X,
                                            const float* __restrict__ b2) {
    __shared__ float Bs[DIM * DIM];
    int t = threadIdx.x;
    for (int i = t; i < DIM * DIM; i += 256) Bs[i] = b2[i];
    __syncthreads();
    int o = t & 31;
    int nb = blockIdx.x * 32 + (t >> 5) * 4;
#pragma unroll
    for (int r = 0; r < 4; r++) {
        int n = nb + r;
        const float* xr = X + (size_t)n * DIM;
        float v = 0.f;
#pragma unroll
        for (int i = 0; i < DIM; i++) v = fmaf(xr[i], Bs[i * DIM + o], v);
        g_Zb[n * DIM + o] = v;
        g_agg[n * DIM + o] = 0.f;
    }
}

// ---------------- K3: FUSED edge MLP (HMMA) + scatter (frozen r16) --------
__global__ void __launch_bounds__(256) k_edge_fused(const float* __restrict__ W1,
                                                    const float* __restrict__ b1,
                                                    const int* __restrict__ esrc,
                                                    const int* __restrict__ edst) {
    __shared__ __half eash[EPB * KP];
    __shared__ __half W1T[EH * KP];
    __shared__ __half hs[EPB * HSP];
    int t = threadIdx.x;
    int e0 = blockIdx.x * EPB;

    {
        const uint4* src = (const uint4*)(g_eah + (size_t)e0 * 96);
        uint4* dst = (uint4*)eash;
#pragma unroll
        for (int idx = t; idx < EPB * 12; idx += 256) {
            int row = idx / 12, q = idx - row * 12;
            dst[row * 13 + q] = src[idx];
        }
    }
    for (int idx = t; idx < EH * 96; idx += 256) {
        int k = idx >> 6, j = idx & 63;
        W1T[j * KP + k] = (k < EFD) ? __float2half(W1[k * EH + j]) : __half(0.f);
    }
    __syncthreads();

    int lane = t & 31, w = t >> 5;
    int lr = lane >> 2, lc = lane & 3;

    {
        int mbase = (w & 3) * 16;
        int jbase = (w >> 2) * 32;
        float c[4][4] = {};
#pragma unroll
        for (int ks = 0; ks < 6; ks++) {
            const __half* ab = &eash[(mbase + lr) * KP + ks * 16 + lc * 2];
            uint32_t a[4];
            a[0] = lds_h2(ab);
            a[1] = lds_h2(ab + 8 * KP);
            a[2] = lds_h2(ab + 8);
            a[3] = lds_h2(ab + 8 * KP + 8);
#pragma unroll
            for (int nt = 0; nt < 4; nt++) {
                const __half* bb = &W1T[(jbase + nt * 8 + lr) * KP + ks * 16 + lc * 2];
                uint32_t b[2];
                b[0] = lds_h2(bb);
                b[1] = lds_h2(bb + 8);
                mma16816(c[nt], a, b);
            }
        }
#pragma unroll
        for (int nt = 0; nt < 4; nt++) {
            int j = jbase + nt * 8 + lc * 2;
            float bx = b1[j], by = b1[j + 1];
            __half2 lo = __floats2half2_rn(fmaxf(c[nt][0] + bx, 0.f),
                                           fmaxf(c[nt][1] + by, 0.f));
            __half2 hi = __floats2half2_rn(fmaxf(c[nt][2] + bx, 0.f),
                                           fmaxf(c[nt][3] + by, 0.f));
            *(uint32_t*)&hs[(mbase + lr) * HSP + j] = *(uint32_t*)&lo;
            *(uint32_t*)&hs[(mbase + lr + 8) * HSP + j] = *(uint32_t*)&hi;
        }
    }
    __syncthreads();

#pragma unroll
    for (int rnd = 0; rnd < 8; rnd++) {
        int eloc = rnd * 8 + w;
        int e = e0 + eloc;
        int s = esrc[e], d = edst[e];
        const __half* zr = g_Zh + (size_t)s * ZCOLS + lane * 8;
        const __half* hr = &hs[eloc * HSP];
        float msg0 = g_Zb[s * DIM + lane];
        float msg1 = 0.f;
#pragma unroll
        for (int kb = 0; kb < 8; kb += 2) {
            uint4 v0 = __ldg((const uint4*)(zr + kb * 256));
            uint4 v1 = __ldg((const uint4*)(zr + (kb + 1) * 256));
            uint4 hh0 = *(const uint4*)(hr + kb * 8);
            uint4 hh1 = *(const uint4*)(hr + kb * 8 + 8);
            float2 h0 = __half22float2(*(__half2*)&hh0.x);
            float2 h1 = __half22float2(*(__half2*)&hh0.y);
            float2 h2 = __half22float2(*(__half2*)&hh0.z);
            float2 h3 = __half22float2(*(__half2*)&hh0.w);
            float2 h4 = __half22float2(*(__half2*)&hh1.x);
            float2 h5 = __half22float2(*(__half2*)&hh1.y);
            float2 h6 = __half22float2(*(__half2*)&hh1.z);
            float2 h7 = __half22float2(*(__half2*)&hh1.w);
            float2 a0 = __half22float2(*(__half2*)&v0.x);
            float2 a1 = __half22float2(*(__half2*)&v0.y);
            float2 a2 = __half22float2(*(__half2*)&v0.z);
            float2 a3 = __half22float2(*(__half2*)&v0.w);
            float2 b0 = __half22float2(*(__half2*)&v1.x);
            float2 b1f = __half22float2(*(__half2*)&v1.y);
            float2 b2f = __half22float2(*(__half2*)&v1.z);
            float2 b3f = __half22float2(*(__half2*)&v1.w);
            msg0 = fmaf(h0.x, a0.x, msg0);
            msg1 = fmaf(h0.y, a0.y, msg1);
            msg0 = fmaf(h1.x, a1.x, msg0);
            msg1 = fmaf(h1.y, a1.y, msg1);
            msg0 = fmaf(h2.x, a2.x, msg0);
            msg1 = fmaf(h2.y, a2.y, msg1);
            msg0 = fmaf(h3.x, a3.x, msg0);
            msg1 = fmaf(h3.y, a3.y, msg1);
            msg0 = fmaf(h4.x, b0.x, msg0);
            msg1 = fmaf(h4.y, b0.y, msg1);
            msg0 = fmaf(h5.x, b1f.x, msg0);
            msg1 = fmaf(h5.y, b1f.y, msg1);
            msg0 = fmaf(h6.x, b2f.x, msg0);
            msg1 = fmaf(h6.y, b2f.y, msg1);
            msg0 = fmaf(h7.x, b3f.x, msg0);
            msg1 = fmaf(h7.y, b3f.y, msg1);
        }
        atomicAdd(&g_agg[d * DIM + lane], msg0 + msg1);
    }
}

// ---------------- K4: node update, 32 nodes/block (frozen) ----------------
template <bool POOL>
__global__ void __launch_bounds__(256) k_node_update(
        const float* __restrict__ xin,
        const float* __restrict__ root,
        const float* __restrict__ bias,
        const float* __restrict__ bng,
        const float* __restrict__ bnb,
        const float* __restrict__ bnrm,
        const float* __restrict__ bnrv,
        float* __restrict__ xout,
        const int* __restrict__ batch) {
    __shared__ float Rs[DIM * DIM];
    int t = threadIdx.x;
    for (int i = t; i < DIM * DIM; i += 256) Rs[i] = root[i];
    __syncthreads();
    int o = t & 31;
    int nb = blockIdx.x * 32 + (t >> 5) * 4;
    float bs = bias[o];
    float sc = rsqrtf(bnrv[o] + BN_EPS) * bng[o];
    float rm = bnrm[o], bb = bnb[o];
#pragma unroll
    for (int r = 0; r < 4; r++) {
        int n = nb + r;
        const float* xr = xin + (size_t)n * DIM;
        float v = g_agg[n * DIM + o] + bs;
#pragma unroll
        for (int i = 0; i < DIM; i++) v = fmaf(xr[i], Rs[i * DIM + o], v);
        v = (v - rm) * sc + bb;
        v = fmaxf(v, 0.f);
        if (POOL) {
            int b = batch[n];
            atomicMax((int*)&g_pool[b * DIM + o], __float_as_int(v));
        } else {
            xout[n * DIM + o] = v;
        }
    }
}

// ---------------- K6: head ----------------
__global__ void k_head(const float* __restrict__ l1W, const float* __restrict__ l1b,
                       const float* __restrict__ l2W, const float* __restrict__ l2b,
                       float* __restrict__ out) {
    int g = threadIdx.x;
    const float* pr = &g_pool[g * DIM];
    float tbuf[DIM];
#pragma unroll
    for (int j = 0; j < DIM; j++) {
        float v = l1b[j];
#pragma unroll
        for (int i = 0; i < DIM; i++) v = fmaf(pr[i], l1W[i * DIM + j], v);
        tbuf[j] = fmaxf(v, 0.f);
    }
#pragma unroll
    for (int c = 0; c < 2; c++) {
        float v = l2b[c];
#pragma unroll
        for (int j = 0; j < DIM; j++) v = fmaf(tbuf[j], l2W[j * 2 + c], v);
        out[g * 2 + c] = v;
    }
}

// ---------------- launch ----------------
extern "C" void kernel_launch(void* const* d_in, const int* in_sizes, int n_in,
                              void* d_out, int out_size) {
    const float* x     = (const float*)d_in[0];
    const int*   esrc  = (const int*)d_in[1];
    const int*   edst  = (const int*)d_in[2];
    const float* ea    = (const float*)d_in[3];
    const int*   batch = (const int*)d_in[4];

    const float* c0W1 = (const float*)d_in[5];
    const float* c0b1 = (const float*)d_in[6];
    const float* c0W2 = (const float*)d_in[7];
    const float* c0b2 = (const float*)d_in[8];
    const float* c0rt = (const float*)d_in[9];
    const float* c0bs = (const float*)d_in[10];
    const float* bn0g = (const float*)d_in[11];
    const float* bn0b = (const float*)d_in[12];
    const float* bn0m = (const float*)d_in[13];
    const float* bn0v = (const float*)d_in[14];

    const float* c1W1 = (const float*)d_in[15];
    const float* c1b1 = (const float*)d_in[16];
    const float* c1W2 = (const float*)d_in[17];
    const float* c1b2 = (const float*)d_in[18];
    const float* c1rt = (const float*)d_in[19];
    const float* c1bs = (const float*)d_in[20];
    const float* bn1g = (const float*)d_in[21];
    const float* bn1b = (const float*)d_in[22];
    const float* bn1m = (const float*)d_in[23];
    const float* bn1v = (const float*)d_in[24];

    const float* l1W = (const float*)d_in[25];
    const float* l1b = (const float*)d_in[26];
    const float* l2W = (const float*)d_in[27];
    const float* l2b = (const float*)d_in[28];

    float* out = (float*)d_out;

    void* px1 = nullptr;
    cudaGetSymbolAddress(&px1, g_x1);
    float* x1 = (float*)px1;

    dim3 zg(8, (N_NODES + 127) / 128);      // 8 x 157

    // ---- prep (pool zero folded into ea2h block 0) ----
    k_ea2h<<<N_EDGES / 32, 256>>>(ea);

    // ---- conv0 ----
    k_zgemm<<<zg, 256>>>(x, c0W2);
    k_zb<<<N_NODES / 32, 256>>>(x, c0b2);   // also zeroes g_agg
    k_edge_fused<<<N_EDGES / EPB, 256>>>(c0W1, c0b1, esrc, edst);
    k_node_update<false><<<N_NODES / 32, 256>>>(x, c0rt, c0bs, bn0g, bn0b,
                                                bn0m, bn0v, x1, nullptr);

    // ---- conv1 ----
    k_zgemm<<<zg, 256>>>(x1, c1W2);
    k_zb<<<N_NODES / 32, 256>>>(x1, c1b2);  // also zeroes g_agg
    k_edge_fused<<<N_EDGES / EPB, 256>>>(c1W1, c1b1, esrc, edst);
    k_node_update<true><<<N_NODES / 32, 256>>>(x1, c1rt, c1bs, bn1g, bn1b,
                                               bn1m, bn1v, nullptr, batch);

    // ---- head ----
    k_head<<<1, NG>>>(l1W, l1b, l2W, l2b, out);
}